// round 3
// baseline (speedup 1.0000x reference)
#include <cuda_runtime.h>
#include <cstdint>

// ---------------------------------------------------------------------------
// SinkhornAttention: BS=4, SEQ=4096, DM=1024, H=16, HD=64, BLK=128, NB=32
// ---------------------------------------------------------------------------
#define BS   4
#define SEQ  4096
#define DM   1024
#define NH   16
#define HD   64
#define BLKS 128
#define NB   32
#define ROWS (BS*SEQ)            // 16384
#define HID  (NH*HD)             // 1024
#define PERB (SEQ*HID)           // 4194304 elems per batch
#define PERBLK (BLKS*HID)        // 131072 elems per 128-token block

// Scratch (device globals: allocation-free per harness rules)
__device__ float g_q [ROWS*HID];
__device__ float g_k [ROWS*HID];
__device__ float g_v [ROWS*HID];
__device__ float g_sk[ROWS*HID];
__device__ float g_sv[ROWS*HID];
__device__ float g_x [ROWS*HID];
__device__ float g_sortout[BS*NB*NB];
__device__ float g_perm   [BS*NB*NB];

// ---------------------------------------------------------------------------
// Tiled fp32 GEMM: C[M,N] = A[M,K] * B[K,N] + bias[N]
// 128x128 tile, 256 threads, 8x8 per thread, K-step 8.
// ---------------------------------------------------------------------------
__global__ __launch_bounds__(256)
void sgemm_bias(const float* __restrict__ A, const float* __restrict__ B,
                const float* __restrict__ bias, float* __restrict__ C,
                int M, int N, int K) {
    __shared__ __align__(16) float As[8][128];
    __shared__ __align__(16) float Bs[8][128];

    const int t  = threadIdx.x;
    const int tx = t & 15;          // 0..15 -> col group
    const int ty = t >> 4;          // 0..15 -> row group
    const int bx = blockIdx.x * 128;
    const int by = blockIdx.y * 128;

    const int aRow = t >> 1;        // 0..127
    const int aCol = (t & 1) * 4;   // 0 or 4
    const int bRow = t >> 5;        // 0..7
    const int bCol = (t & 31) * 4;  // 0..124

    const float* Aptr = A + (by + aRow) * K + aCol;
    const float* Bptr = B + bRow * N + bx + bCol;

    float acc[8][8];
    #pragma unroll
    for (int i = 0; i < 8; i++)
        #pragma unroll
        for (int j = 0; j < 8; j++) acc[i][j] = 0.f;

    for (int k0 = 0; k0 < K; k0 += 8) {
        float4 av = *(const float4*)(Aptr + k0);
        float4 bv = *(const float4*)(Bptr + (size_t)k0 * N);
        As[aCol + 0][aRow] = av.x;
        As[aCol + 1][aRow] = av.y;
        As[aCol + 2][aRow] = av.z;
        As[aCol + 3][aRow] = av.w;
        *(float4*)&Bs[bRow][bCol] = bv;
        __syncthreads();

        #pragma unroll
        for (int kk = 0; kk < 8; kk++) {
            float a[8], b[8];
            float4 a0 = *(const float4*)&As[kk][ty * 8];
            float4 a1 = *(const float4*)&As[kk][ty * 8 + 4];
            float4 b0 = *(const float4*)&Bs[kk][tx * 8];
            float4 b1 = *(const float4*)&Bs[kk][tx * 8 + 4];
            a[0]=a0.x; a[1]=a0.y; a[2]=a0.z; a[3]=a0.w;
            a[4]=a1.x; a[5]=a1.y; a[6]=a1.z; a[7]=a1.w;
            b[0]=b0.x; b[1]=b0.y; b[2]=b0.z; b[3]=b0.w;
            b[4]=b1.x; b[5]=b1.y; b[6]=b1.z; b[7]=b1.w;
            #pragma unroll
            for (int i = 0; i < 8; i++)
                #pragma unroll
                for (int j = 0; j < 8; j++)
                    acc[i][j] += a[i] * b[j];
        }
        __syncthreads();
    }

    #pragma unroll
    for (int i = 0; i < 8; i++) {
        int row = by + ty * 8 + i;
        #pragma unroll
        for (int j = 0; j < 8; j += 4) {
            int col = bx + tx * 8 + j;
            float4 o;
            o.x = acc[i][j+0] + bias[col+0];
            o.y = acc[i][j+1] + bias[col+1];
            o.z = acc[i][j+2] + bias[col+2];
            o.w = acc[i][j+3] + bias[col+3];
            *(float4*)(C + (size_t)row * N + col) = o;
        }
    }
}

// ---------------------------------------------------------------------------
// sum_key over each 128-token block + sort logits:  g_sortout[b][n][m]
// grid = BS*NB blocks, 256 threads.
// ---------------------------------------------------------------------------
__global__ __launch_bounds__(256)
void sumkey_sort(const float* __restrict__ w_sort, const float* __restrict__ b_sort) {
    __shared__ float sk[HID];
    const int bn = blockIdx.x;
    const int b = bn >> 5, n = bn & 31;
    const int t = threadIdx.x;

    const float* base = g_k + ((size_t)(b * SEQ + n * BLKS)) * HID;
    for (int c = t; c < HID; c += 256) {
        float s = 0.f;
        for (int r = 0; r < BLKS; r++) s += base[(size_t)r * HID + c];
        sk[c] = s;
    }
    __syncthreads();

    const int warp = t >> 5, lane = t & 31;
    for (int m = warp; m < NB; m += 8) {
        float s = 0.f;
        for (int c = lane; c < HID; c += 32) s += sk[c] * w_sort[c * NB + m];
        #pragma unroll
        for (int o = 16; o; o >>= 1) s += __shfl_xor_sync(0xffffffffu, s, o);
        if (lane == 0) g_sortout[b * (NB*NB) + n * NB + m] = s + b_sort[m];
    }
}

// ---------------------------------------------------------------------------
// Sinkhorn: 5 iterations of row/col logsumexp normalization on 32x32, per batch.
// grid = BS, block (32,32).
// ---------------------------------------------------------------------------
__global__ void sinkhorn_kernel() {
    __shared__ float la[32][33];
    __shared__ float colLse[32];
    const int b = blockIdx.x;
    const int j = threadIdx.x, i = threadIdx.y;

    float v = g_sortout[b * (NB*NB) + i * NB + j];   // TEMP = 1

    for (int it = 0; it < 5; it++) {
        // logsumexp over axis=2 (row i, reduce over j) -- warp reduction
        float mx = v;
        #pragma unroll
        for (int o = 16; o; o >>= 1) mx = fmaxf(mx, __shfl_xor_sync(0xffffffffu, mx, o));
        float sum = expf(v - mx);
        #pragma unroll
        for (int o = 16; o; o >>= 1) sum += __shfl_xor_sync(0xffffffffu, sum, o);
        v -= mx + logf(sum);

        la[i][j] = v;
        __syncthreads();

        // logsumexp over axis=1 (column, reduce over i): warp i handles column i
        float cv = la[j][i];
        float cm = cv;
        #pragma unroll
        for (int o = 16; o; o >>= 1) cm = fmaxf(cm, __shfl_xor_sync(0xffffffffu, cm, o));
        float cs = expf(cv - cm);
        #pragma unroll
        for (int o = 16; o; o >>= 1) cs += __shfl_xor_sync(0xffffffffu, cs, o);
        if (j == 0) colLse[i] = cm + logf(cs);
        __syncthreads();

        v -= colLse[j];
        __syncthreads();
    }
    g_perm[b * (NB*NB) + i * NB + j] = expf(fminf(fmaxf(v, -1.f), 1.f));
}

// ---------------------------------------------------------------------------
// sorted_k / sorted_v = perm @ blocks.  Each source element read exactly once.
// grid = (128 chunks, BS, 2), 256 threads; each thread owns 4 cols x 32 n accs.
// ---------------------------------------------------------------------------
__global__ __launch_bounds__(256)
void blockmix() {
    __shared__ float p[NB][NB];
    const int b = blockIdx.y;
    const int which = blockIdx.z;
    const float* __restrict__ src = which ? g_v : g_k;
    float* __restrict__ dst = which ? g_sv : g_sk;

    const int t = threadIdx.x;
    for (int i = t; i < NB * NB; i += 256) p[i / NB][i % NB] = g_perm[b * (NB*NB) + i];
    __syncthreads();

    const size_t base = (size_t)b * PERB + (size_t)blockIdx.x * 1024;

    float acc[NB * 4];
    #pragma unroll
    for (int i = 0; i < NB * 4; i++) acc[i] = 0.f;

    for (int m = 0; m < NB; m++) {
        float kv[4];
        #pragma unroll
        for (int jj = 0; jj < 4; jj++)
            kv[jj] = src[base + (size_t)m * PERBLK + t + 256 * jj];
        #pragma unroll
        for (int n = 0; n < NB; n++) {
            float pm = p[n][m];
            #pragma unroll
            for (int jj = 0; jj < 4; jj++) acc[n * 4 + jj] += pm * kv[jj];
        }
    }

    #pragma unroll
    for (int n = 0; n < NB; n++)
        #pragma unroll
        for (int jj = 0; jj < 4; jj++)
            dst[base + (size_t)n * PERBLK + t + 256 * jj] = acc[n * 4 + jj];
}

// ---------------------------------------------------------------------------
// Block attention: per (h, n, b): Q(128x64) vs Kcat/Vcat(256x64), online softmax.
// 128 threads (one per query row), K/V chunks of 32 staged in shared,
// scores staged in shared to keep register indexing static.
// ---------------------------------------------------------------------------
__global__ __launch_bounds__(128)
void attn_kernel() {
    __shared__ __align__(16) float Ks[32][64];
    __shared__ __align__(16) float Vs[32][64];
    __shared__ float Ss[32][128];

    const int h = blockIdx.x, n = blockIdx.y, b = blockIdx.z;
    const int t = threadIdx.x;
    const float scale = 0.125f;  // 1/sqrt(64)

    const size_t qbase = ((size_t)(b * SEQ + n * BLKS + t)) * HID + h * HD;
    float qr[HD];
    #pragma unroll
    for (int d = 0; d < HD; d += 4) {
        float4 f = *(const float4*)(g_q + qbase + d);
        qr[d]   = f.x * scale; qr[d+1] = f.y * scale;
        qr[d+2] = f.z * scale; qr[d+3] = f.w * scale;
    }

    float o[HD];
    #pragma unroll
    for (int d = 0; d < HD; d++) o[d] = 0.f;
    float mrun = -1e30f, lrun = 0.f;

    const int r  = t >> 2;          // 0..31 row within chunk
    const int q4 = (t & 3) * 16;    // quarter of the 64-wide row

    for (int kc = 0; kc < 8; kc++) {
        const int jg = kc * 32 + r;            // 0..255 global key index
        const float *kp, *vp;
        if (jg < BLKS) {
            size_t off = ((size_t)(b * SEQ + n * BLKS + jg)) * HID + h * HD + q4;
            kp = g_k + off; vp = g_v + off;
        } else {
            size_t off = (size_t)b * PERB + (size_t)n * PERBLK
                       + (size_t)(jg - BLKS) * HID + h * HD + q4;
            kp = g_sk + off; vp = g_sv + off;
        }
        #pragma unroll
        for (int u = 0; u < 4; u++) {
            *(float4*)&Ks[r][q4 + u * 4] = *(const float4*)(kp + u * 4);
            *(float4*)&Vs[r][q4 + u * 4] = *(const float4*)(vp + u * 4);
        }
        __syncthreads();

        // scores for this chunk
        float cmax = -1e30f;
        #pragma unroll 4
        for (int j = 0; j < 32; j++) {
            float acc = 0.f;
            #pragma unroll
            for (int d = 0; d < HD; d += 4) {
                float4 kk = *(const float4*)&Ks[j][d];
                acc += qr[d] * kk.x + qr[d+1] * kk.y + qr[d+2] * kk.z + qr[d+3] * kk.w;
            }
            Ss[j][t] = acc;
            cmax = fmaxf(cmax, acc);
        }

        float nm   = fmaxf(mrun, cmax);
        float corr = __expf(mrun - nm);
        lrun *= corr;
        #pragma unroll
        for (int d = 0; d < HD; d++) o[d] *= corr;

        #pragma unroll 4
        for (int j = 0; j < 32; j++) {
            float pw = __expf(Ss[j][t] - nm);
            lrun += pw;
            #pragma unroll
            for (int d = 0; d < HD; d += 4) {
                float4 vv = *(const float4*)&Vs[j][d];
                o[d]   += pw * vv.x; o[d+1] += pw * vv.y;
                o[d+2] += pw * vv.z; o[d+3] += pw * vv.w;
            }
        }
        mrun = nm;
        __syncthreads();
    }

    const float inv = 1.f / lrun;
    #pragma unroll
    for (int d = 0; d < HD; d += 4) {
        float4 f;
        f.x = o[d] * inv; f.y = o[d+1] * inv;
        f.z = o[d+2] * inv; f.w = o[d+3] * inv;
        *(float4*)(g_x + qbase + d) = f;
    }
}

// ---------------------------------------------------------------------------
// Host launcher
// ---------------------------------------------------------------------------
extern "C" void kernel_launch(void* const* d_in, const int* in_sizes, int n_in,
                              void* d_out, int out_size) {
    const float* inputs_q = (const float*)d_in[0];
    const float* wq = (const float*)d_in[1];
    const float* bq = (const float*)d_in[2];
    const float* wk = (const float*)d_in[3];
    const float* bk = (const float*)d_in[4];
    const float* wv = (const float*)d_in[5];
    const float* bv = (const float*)d_in[6];
    const float* w_sort = (const float*)d_in[7];
    const float* b_sort = (const float*)d_in[8];
    const float* wo = (const float*)d_in[9];
    const float* bo = (const float*)d_in[10];
    float* out = (float*)d_out;

    float *pq, *pk, *pv, *px;
    cudaGetSymbolAddress((void**)&pq, g_q);
    cudaGetSymbolAddress((void**)&pk, g_k);
    cudaGetSymbolAddress((void**)&pv, g_v);
    cudaGetSymbolAddress((void**)&px, g_x);

    dim3 gg(HID / 128, ROWS / 128);
    sgemm_bias<<<gg, 256>>>(inputs_q, wq, bq, pq, ROWS, HID, DM);
    sgemm_bias<<<gg, 256>>>(inputs_q, wk, bk, pk, ROWS, HID, DM);
    sgemm_bias<<<gg, 256>>>(inputs_q, wv, bv, pv, ROWS, HID, DM);

    sumkey_sort<<<BS * NB, 256>>>(w_sort, b_sort);
    sinkhorn_kernel<<<BS, dim3(32, 32)>>>();
    blockmix<<<dim3(PERBLK / 1024, BS, 2), 256>>>();
    attn_kernel<<<dim3(NH, NB, BS), 128>>>();

    sgemm_bias<<<gg, 256>>>(px, wo, bo, out, ROWS, HID, DM);
}

// round 5
// speedup vs baseline: 1.8272x; 1.8272x over previous
#include <cuda_runtime.h>
#include <cuda_bf16.h>
#include <cstdint>

// ---------------------------------------------------------------------------
// SinkhornAttention: BS=4, SEQ=4096, DM=1024, H=16, HD=64, BLK=128, NB=32
// ---------------------------------------------------------------------------
#define BS   4
#define SEQ  4096
#define DM   1024
#define NH   16
#define HD   64
#define BLKS 128
#define NB   32
#define ROWS (BS*SEQ)            // 16384
#define HID  (NH*HD)             // 1024
#define PERB (SEQ*HID)
#define PERBLK (BLKS*HID)

// GEMM tiling (mma.sync path; tcgen05 not available on compute_103 base target)
#define TM 128
#define TN 128
#define KC 32                       // k per chunk (bf16)
#define NCHUNK (DM / KC)            // 32
#define ROWB 80                     // 64B data + 16B pad per 32-k row
#define MATB (128 * ROWB)           // 10240 bytes per matrix per stage
#define STAGE_BYTES (4 * MATB)      // Ah, Al, Bh, Bl
#define NSTAGE 3
#define GEMM_SMEM (NSTAGE * STAGE_BYTES)   // 122880

// ---------------------------------------------------------------------------
// Scratch (device globals: allocation-free per harness rules)
// ---------------------------------------------------------------------------
__device__ float g_q [ROWS*HID];
__device__ float g_k [ROWS*HID];
__device__ float g_v [ROWS*HID];
__device__ float g_sk[ROWS*HID];
__device__ float g_sv[ROWS*HID];
__device__ float g_x [ROWS*HID];
__device__ float g_sortout[BS*NB*NB];
__device__ float g_perm   [BS*NB*NB];

__device__ __nv_bfloat16 g_ah[ROWS*DM];   // inputs_q hi
__device__ __nv_bfloat16 g_al[ROWS*DM];   // inputs_q lo
__device__ __nv_bfloat16 g_xh[ROWS*HID];  // attention output hi
__device__ __nv_bfloat16 g_xl[ROWS*HID];  // attention output lo
__device__ __nv_bfloat16 g_wqh[HID*DM], g_wql[HID*DM];  // transposed [n][k]
__device__ __nv_bfloat16 g_wkh[HID*DM], g_wkl[HID*DM];
__device__ __nv_bfloat16 g_wvh[HID*DM], g_wvl[HID*DM];
__device__ __nv_bfloat16 g_woh[DM*HID],  g_wol[DM*HID];

// ---------------------------------------------------------------------------
// PTX helpers (base-target-safe: cp.async / ldmatrix / mma.sync only)
// ---------------------------------------------------------------------------
__device__ __forceinline__ void cp16(uint32_t s, const void* g) {
    asm volatile("cp.async.cg.shared.global [%0], [%1], 16;" :: "r"(s), "l"(g));
}
#define CP_COMMIT() asm volatile("cp.async.commit_group;" ::: "memory")
#define CP_WAIT(n)  asm volatile("cp.async.wait_group %0;" :: "n"(n) : "memory")

__device__ __forceinline__ void ldsm4(uint32_t* r, uint32_t addr) {
    asm volatile("ldmatrix.sync.aligned.m8n8.x4.shared.b16 {%0,%1,%2,%3}, [%4];"
                 : "=r"(r[0]), "=r"(r[1]), "=r"(r[2]), "=r"(r[3]) : "r"(addr));
}
__device__ __forceinline__ void mma16816(float* c, const uint32_t* a,
                                         uint32_t b0, uint32_t b1) {
    asm volatile("mma.sync.aligned.m16n8k16.row.col.f32.bf16.bf16.f32 "
                 "{%0,%1,%2,%3}, {%4,%5,%6,%7}, {%8,%9}, {%0,%1,%2,%3};"
                 : "+f"(c[0]), "+f"(c[1]), "+f"(c[2]), "+f"(c[3])
                 : "r"(a[0]), "r"(a[1]), "r"(a[2]), "r"(a[3]), "r"(b0), "r"(b1));
}

// ---------------------------------------------------------------------------
// Split fp32 -> (hi, lo) bf16
// ---------------------------------------------------------------------------
__global__ __launch_bounds__(256)
void split_bf16(const float* __restrict__ src, __nv_bfloat16* __restrict__ hi,
                __nv_bfloat16* __restrict__ lo, int n4) {
    int i = blockIdx.x * 256 + threadIdx.x;
    if (i >= n4) return;
    float4 f = ((const float4*)src)[i];
    __nv_bfloat16 h0 = __float2bfloat16(f.x), h1 = __float2bfloat16(f.y);
    __nv_bfloat16 h2 = __float2bfloat16(f.z), h3 = __float2bfloat16(f.w);
    __nv_bfloat162 hA, hB, lA, lB;
    hA.x = h0; hA.y = h1; hB.x = h2; hB.y = h3;
    lA.x = __float2bfloat16(f.x - __bfloat162float(h0));
    lA.y = __float2bfloat16(f.y - __bfloat162float(h1));
    lB.x = __float2bfloat16(f.z - __bfloat162float(h2));
    lB.y = __float2bfloat16(f.w - __bfloat162float(h3));
    ((__nv_bfloat162*)hi)[i*2]   = hA;
    ((__nv_bfloat162*)hi)[i*2+1] = hB;
    ((__nv_bfloat162*)lo)[i*2]   = lA;
    ((__nv_bfloat162*)lo)[i*2+1] = lB;
}

// ---------------------------------------------------------------------------
// Transpose 1024x1024 fp32 W[k][n] -> bf16 hi/lo Wt[n][k]
// ---------------------------------------------------------------------------
__global__ __launch_bounds__(256)
void transpose_split(const float* __restrict__ W, __nv_bfloat16* __restrict__ hi,
                     __nv_bfloat16* __restrict__ lo) {
    __shared__ float t[32][33];
    const int tx = threadIdx.x, ty = threadIdx.y;
    const int x = blockIdx.x * 32 + tx;
    const int y0 = blockIdx.y * 32;
    #pragma unroll
    for (int i = ty; i < 32; i += 8) t[i][tx] = W[(size_t)(y0 + i) * 1024 + x];
    __syncthreads();
    const int k = y0 + tx;
    #pragma unroll
    for (int i = ty; i < 32; i += 8) {
        int n = blockIdx.x * 32 + i;
        float v = t[tx][i];
        __nv_bfloat16 h = __float2bfloat16(v);
        hi[(size_t)n * 1024 + k] = h;
        lo[(size_t)n * 1024 + k] = __float2bfloat16(v - __bfloat162float(h));
    }
}

// ---------------------------------------------------------------------------
// HMMA GEMM: C[16384,1024] = (Ah+Al)[M,K] * (Bh+Bl)[n][k]^T + bias
//   3-pass hi/lo bf16 mma.sync m16n8k16, fp32 register accumulators.
//   CTA tile 128x128, 8 warps (2M x 4N), warp tile 64x32, KC=32, 3-stage cp.async.
// ---------------------------------------------------------------------------
__global__ __launch_bounds__(256, 1)
void gemm_hmma(const __nv_bfloat16* __restrict__ Ah, const __nv_bfloat16* __restrict__ Al,
               const __nv_bfloat16* __restrict__ Bh, const __nv_bfloat16* __restrict__ Bl,
               const float* __restrict__ bias, float* __restrict__ C) {
    extern __shared__ __align__(128) char smem[];
    const uint32_t sbase = (uint32_t)__cvta_generic_to_shared(smem);

    const int tid  = threadIdx.x;
    const int wid  = tid >> 5, lane = tid & 31;
    const int wm   = wid >> 2;          // 0..1  (M)
    const int wn   = wid & 3;           // 0..3  (N)
    const int bx0  = blockIdx.x * TN;
    const int by0  = blockIdx.y * TM;

    // --- cp.async mapping: thread t loads rows (t>>2) and (t>>2)+64, 16B chunk t&3
    const int rr  = tid >> 2;
    const int c16 = tid & 3;

    auto load_stage = [&](int c, int s) {
        const uint32_t st = sbase + (uint32_t)s * STAGE_BYTES;
        const size_t kof = (size_t)c * KC + c16 * 8;
        #pragma unroll
        for (int i = 0; i < 2; i++) {
            const int row = rr + i * 64;
            const uint32_t so = (uint32_t)(row * ROWB + c16 * 16);
            const size_t ga = (size_t)(by0 + row) * DM + kof;
            const size_t gb = (size_t)(bx0 + row) * DM + kof;
            cp16(st +            so, Ah + ga);
            cp16(st +     MATB + so, Al + ga);
            cp16(st + 2 * MATB + so, Bh + gb);
            cp16(st + 3 * MATB + so, Bl + gb);
        }
    };

    // --- ldmatrix per-lane address components
    const int mi   = lane >> 3;          // matrix index within x4
    const int lrow = lane & 7;
    // A x4: matrices (rows+0,k+0),(rows+8,k+0),(rows+0,k+16B),(rows+8,k+16B)
    const uint32_t aoff = (uint32_t)(((mi & 1) * 8 + lrow) * ROWB + (mi >> 1) * 16);
    // B x4: matrices (n+0,k+0),(n+0,k+16B),(n+8,k+0),(n+8,k+16B)
    const uint32_t boff = (uint32_t)(((mi >> 1) * 8 + lrow) * ROWB + (mi & 1) * 16);

    float acc[16][4];
    #pragma unroll
    for (int i = 0; i < 16; i++)
        #pragma unroll
        for (int j = 0; j < 4; j++) acc[i][j] = 0.f;

    load_stage(0, 0); CP_COMMIT();
    load_stage(1, 1); CP_COMMIT();

    for (int c = 0; c < NCHUNK; c++) {
        if (c + 2 < NCHUNK) load_stage(c + 2, (c + 2) % NSTAGE);
        CP_COMMIT();
        CP_WAIT(2);
        __syncthreads();

        const uint32_t st = sbase + (uint32_t)(c % NSTAGE) * STAGE_BYTES;
        const uint32_t sAh = st, sAl = st + MATB, sBh = st + 2*MATB, sBl = st + 3*MATB;

        #pragma unroll
        for (int ks = 0; ks < 2; ks++) {
            const uint32_t kb = ks * 32;
            uint32_t ah[4][4], al[4][4], bh[2][4], bl[2][4];
            #pragma unroll
            for (int mt = 0; mt < 4; mt++) {
                const uint32_t ro = (uint32_t)((wm * 64 + mt * 16) * ROWB) + kb + aoff;
                ldsm4(ah[mt], sAh + ro);
                ldsm4(al[mt], sAl + ro);
            }
            #pragma unroll
            for (int nt2 = 0; nt2 < 2; nt2++) {
                const uint32_t ro = (uint32_t)((wn * 32 + nt2 * 16) * ROWB) + kb + boff;
                ldsm4(bh[nt2], sBh + ro);
                ldsm4(bl[nt2], sBl + ro);
            }
            #pragma unroll
            for (int mt = 0; mt < 4; mt++)
                #pragma unroll
                for (int nt = 0; nt < 4; nt++) {
                    const int p = nt >> 1, q = (nt & 1) * 2;
                    mma16816(acc[mt*4+nt], ah[mt], bh[p][q], bh[p][q+1]);  // Ah*Bh
                    mma16816(acc[mt*4+nt], ah[mt], bl[p][q], bl[p][q+1]);  // Ah*Bl
                    mma16816(acc[mt*4+nt], al[mt], bh[p][q], bh[p][q+1]);  // Al*Bh
                }
        }
        __syncthreads();
    }

    // Epilogue: c0,c1 -> C[g][2t..], c2,c3 -> C[g+8][2t..]
    const int g = lane >> 2, t2 = (lane & 3) * 2;
    #pragma unroll
    for (int mt = 0; mt < 4; mt++) {
        const int row0 = by0 + wm * 64 + mt * 16 + g;
        #pragma unroll
        for (int nt = 0; nt < 4; nt++) {
            const int col = bx0 + wn * 32 + nt * 8 + t2;
            const float2 bv = *(const float2*)(bias + col);
            float2 o0, o1;
            o0.x = acc[mt*4+nt][0] + bv.x; o0.y = acc[mt*4+nt][1] + bv.y;
            o1.x = acc[mt*4+nt][2] + bv.x; o1.y = acc[mt*4+nt][3] + bv.y;
            *(float2*)(C + (size_t)row0 * HID + col)       = o0;
            *(float2*)(C + (size_t)(row0 + 8) * HID + col) = o1;
        }
    }
}

// ---------------------------------------------------------------------------
// sum_key + sort logits (unchanged)
// ---------------------------------------------------------------------------
__global__ __launch_bounds__(256)
void sumkey_sort(const float* __restrict__ w_sort, const float* __restrict__ b_sort) {
    __shared__ float sk[HID];
    const int bn = blockIdx.x;
    const int b = bn >> 5, n = bn & 31;
    const int t = threadIdx.x;

    const float* base = g_k + ((size_t)(b * SEQ + n * BLKS)) * HID;
    for (int c = t; c < HID; c += 256) {
        float s = 0.f;
        for (int r = 0; r < BLKS; r++) s += base[(size_t)r * HID + c];
        sk[c] = s;
    }
    __syncthreads();

    const int warp = t >> 5, lane = t & 31;
    for (int m = warp; m < NB; m += 8) {
        float s = 0.f;
        for (int c = lane; c < HID; c += 32) s += sk[c] * w_sort[c * NB + m];
        #pragma unroll
        for (int o = 16; o; o >>= 1) s += __shfl_xor_sync(0xffffffffu, s, o);
        if (lane == 0) g_sortout[b * (NB*NB) + n * NB + m] = s + b_sort[m];
    }
}

// ---------------------------------------------------------------------------
// Sinkhorn (unchanged)
// ---------------------------------------------------------------------------
__global__ void sinkhorn_kernel() {
    __shared__ float la[32][33];
    __shared__ float colLse[32];
    const int b = blockIdx.x;
    const int j = threadIdx.x, i = threadIdx.y;

    float v = g_sortout[b * (NB*NB) + i * NB + j];

    for (int it = 0; it < 5; it++) {
        float mx = v;
        #pragma unroll
        for (int o = 16; o; o >>= 1) mx = fmaxf(mx, __shfl_xor_sync(0xffffffffu, mx, o));
        float sum = expf(v - mx);
        #pragma unroll
        for (int o = 16; o; o >>= 1) sum += __shfl_xor_sync(0xffffffffu, sum, o);
        v -= mx + logf(sum);

        la[i][j] = v;
        __syncthreads();

        float cv = la[j][i];
        float cm = cv;
        #pragma unroll
        for (int o = 16; o; o >>= 1) cm = fmaxf(cm, __shfl_xor_sync(0xffffffffu, cm, o));
        float cs = expf(cv - cm);
        #pragma unroll
        for (int o = 16; o; o >>= 1) cs += __shfl_xor_sync(0xffffffffu, cs, o);
        if (j == 0) colLse[i] = cm + logf(cs);
        __syncthreads();

        v -= colLse[j];
        __syncthreads();
    }
    g_perm[b * (NB*NB) + i * NB + j] = expf(fminf(fmaxf(v, -1.f), 1.f));
}

// ---------------------------------------------------------------------------
// blockmix (unchanged)
// ---------------------------------------------------------------------------
__global__ __launch_bounds__(256)
void blockmix() {
    __shared__ float p[NB][NB];
    const int b = blockIdx.y;
    const int which = blockIdx.z;
    const float* __restrict__ src = which ? g_v : g_k;
    float* __restrict__ dst = which ? g_sv : g_sk;

    const int t = threadIdx.x;
    for (int i = t; i < NB * NB; i += 256) p[i / NB][i % NB] = g_perm[b * (NB*NB) + i];
    __syncthreads();

    const size_t base = (size_t)b * PERB + (size_t)blockIdx.x * 1024;

    float acc[NB * 4];
    #pragma unroll
    for (int i = 0; i < NB * 4; i++) acc[i] = 0.f;

    for (int m = 0; m < NB; m++) {
        float kv[4];
        #pragma unroll
        for (int jj = 0; jj < 4; jj++)
            kv[jj] = src[base + (size_t)m * PERBLK + t + 256 * jj];
        #pragma unroll
        for (int n = 0; n < NB; n++) {
            float pm = p[n][m];
            #pragma unroll
            for (int jj = 0; jj < 4; jj++) acc[n * 4 + jj] += pm * kv[jj];
        }
    }

    #pragma unroll
    for (int n = 0; n < NB; n++)
        #pragma unroll
        for (int jj = 0; jj < 4; jj++)
            dst[base + (size_t)n * PERBLK + t + 256 * jj] = acc[n * 4 + jj];
}

// ---------------------------------------------------------------------------
// Block attention (unchanged)
// ---------------------------------------------------------------------------
__global__ __launch_bounds__(128)
void attn_kernel() {
    __shared__ __align__(16) float Ks[32][64];
    __shared__ __align__(16) float Vs[32][64];
    __shared__ float Ss[32][128];

    const int h = blockIdx.x, n = blockIdx.y, b = blockIdx.z;
    const int t = threadIdx.x;
    const float scale = 0.125f;

    const size_t qbase = ((size_t)(b * SEQ + n * BLKS + t)) * HID + h * HD;
    float qr[HD];
    #pragma unroll
    for (int d = 0; d < HD; d += 4) {
        float4 f = *(const float4*)(g_q + qbase + d);
        qr[d]   = f.x * scale; qr[d+1] = f.y * scale;
        qr[d+2] = f.z * scale; qr[d+3] = f.w * scale;
    }

    float o[HD];
    #pragma unroll
    for (int d = 0; d < HD; d++) o[d] = 0.f;
    float mrun = -1e30f, lrun = 0.f;

    const int r  = t >> 2;
    const int q4 = (t & 3) * 16;

    for (int kc = 0; kc < 8; kc++) {
        const int jg = kc * 32 + r;
        const float *kp, *vp;
        if (jg < BLKS) {
            size_t off = ((size_t)(b * SEQ + n * BLKS + jg)) * HID + h * HD + q4;
            kp = g_k + off; vp = g_v + off;
        } else {
            size_t off = (size_t)b * PERB + (size_t)n * PERBLK
                       + (size_t)(jg - BLKS) * HID + h * HD + q4;
            kp = g_sk + off; vp = g_sv + off;
        }
        #pragma unroll
        for (int uu = 0; uu < 4; uu++) {
            *(float4*)&Ks[r][q4 + uu * 4] = *(const float4*)(kp + uu * 4);
            *(float4*)&Vs[r][q4 + uu * 4] = *(const float4*)(vp + uu * 4);
        }
        __syncthreads();

        float cmax = -1e30f;
        #pragma unroll 4
        for (int j = 0; j < 32; j++) {
            float acc = 0.f;
            #pragma unroll
            for (int d = 0; d < HD; d += 4) {
                float4 kk = *(const float4*)&Ks[j][d];
                acc += qr[d] * kk.x + qr[d+1] * kk.y + qr[d+2] * kk.z + qr[d+3] * kk.w;
            }
            Ss[j][t] = acc;
            cmax = fmaxf(cmax, acc);
        }

        float nm   = fmaxf(mrun, cmax);
        float corr = __expf(mrun - nm);
        lrun *= corr;
        #pragma unroll
        for (int d = 0; d < HD; d++) o[d] *= corr;

        #pragma unroll 4
        for (int j = 0; j < 32; j++) {
            float pw = __expf(Ss[j][t] - nm);
            lrun += pw;
            #pragma unroll
            for (int d = 0; d < HD; d += 4) {
                float4 vv = *(const float4*)&Vs[j][d];
                o[d]   += pw * vv.x; o[d+1] += pw * vv.y;
                o[d+2] += pw * vv.z; o[d+3] += pw * vv.w;
            }
        }
        mrun = nm;
        __syncthreads();
    }

    const float inv = 1.f / lrun;
    #pragma unroll
    for (int d = 0; d < HD; d += 4) {
        float4 f;
        f.x = o[d] * inv; f.y = o[d+1] * inv;
        f.z = o[d+2] * inv; f.w = o[d+3] * inv;
        *(float4*)(g_x + qbase + d) = f;
    }
}

// ---------------------------------------------------------------------------
// Host launcher
// ---------------------------------------------------------------------------
extern "C" void kernel_launch(void* const* d_in, const int* in_sizes, int n_in,
                              void* d_out, int out_size) {
    const float* inputs_q = (const float*)d_in[0];
    const float* wq = (const float*)d_in[1];
    const float* bq = (const float*)d_in[2];
    const float* wk = (const float*)d_in[3];
    const float* bk = (const float*)d_in[4];
    const float* wv = (const float*)d_in[5];
    const float* bv = (const float*)d_in[6];
    const float* w_sort = (const float*)d_in[7];
    const float* b_sort = (const float*)d_in[8];
    const float* wo = (const float*)d_in[9];
    const float* bo = (const float*)d_in[10];
    float* out = (float*)d_out;

    float *pq, *pk, *pv, *px;
    cudaGetSymbolAddress((void**)&pq, g_q);
    cudaGetSymbolAddress((void**)&pk, g_k);
    cudaGetSymbolAddress((void**)&pv, g_v);
    cudaGetSymbolAddress((void**)&px, g_x);
    __nv_bfloat16 *ah, *al, *xh, *xl;
    __nv_bfloat16 *wqh, *wql, *wkh, *wkl, *wvh, *wvl, *woh, *wol;
    cudaGetSymbolAddress((void**)&ah, g_ah);
    cudaGetSymbolAddress((void**)&al, g_al);
    cudaGetSymbolAddress((void**)&xh, g_xh);
    cudaGetSymbolAddress((void**)&xl, g_xl);
    cudaGetSymbolAddress((void**)&wqh, g_wqh); cudaGetSymbolAddress((void**)&wql, g_wql);
    cudaGetSymbolAddress((void**)&wkh, g_wkh); cudaGetSymbolAddress((void**)&wkl, g_wkl);
    cudaGetSymbolAddress((void**)&wvh, g_wvh); cudaGetSymbolAddress((void**)&wvl, g_wvl);
    cudaGetSymbolAddress((void**)&woh, g_woh); cudaGetSymbolAddress((void**)&wol, g_wol);

    cudaFuncSetAttribute(gemm_hmma, cudaFuncAttributeMaxDynamicSharedMemorySize, GEMM_SMEM);

    const int n4 = ROWS * DM / 4;
    split_bf16<<<(n4 + 255) / 256, 256>>>(inputs_q, ah, al, n4);
    dim3 tg(32, 32);
    transpose_split<<<tg, dim3(32, 8)>>>(wq, wqh, wql);
    transpose_split<<<tg, dim3(32, 8)>>>(wk, wkh, wkl);
    transpose_split<<<tg, dim3(32, 8)>>>(wv, wvh, wvl);
    transpose_split<<<tg, dim3(32, 8)>>>(wo, woh, wol);

    dim3 gg(HID / TN, ROWS / TM);
    gemm_hmma<<<gg, 256, GEMM_SMEM>>>(ah, al, wqh, wql, bq, pq);
    gemm_hmma<<<gg, 256, GEMM_SMEM>>>(ah, al, wkh, wkl, bk, pk);
    gemm_hmma<<<gg, 256, GEMM_SMEM>>>(ah, al, wvh, wvl, bv, pv);

    sumkey_sort<<<BS * NB, 256>>>(w_sort, b_sort);
    sinkhorn_kernel<<<BS, dim3(32, 32)>>>();
    blockmix<<<dim3(PERBLK / 1024, BS, 2), 256>>>();
    attn_kernel<<<dim3(NH, NB, BS), 128>>>();

    split_bf16<<<(n4 + 255) / 256, 256>>>(px, xh, xl, n4);
    gemm_hmma<<<gg, 256, GEMM_SMEM>>>(xh, xl, woh, wol, bo, out);
}

// round 6
// speedup vs baseline: 2.6670x; 1.4596x over previous
#include <cuda_runtime.h>
#include <cuda_fp16.h>
#include <cstdint>

// ---------------------------------------------------------------------------
// SinkhornAttention: BS=4, SEQ=4096, DM=1024, H=16, HD=64, BLK=128, NB=32
// ---------------------------------------------------------------------------
#define BS   4
#define SEQ  4096
#define DM   1024
#define NH   16
#define HD   64
#define BLKS 128
#define NB   32
#define ROWS (BS*SEQ)            // 16384
#define HID  (NH*HD)             // 1024
#define PERB (SEQ*HID)
#define PERBLK (BLKS*HID)

// GEMM tiling (single-pass fp16 mma.sync; tcgen05 unavailable on compute_103)
#define TM 128
#define TN 128
#define KC 32                       // k per chunk (fp16)
#define NCHUNK (DM / KC)            // 32
#define ROWB 80                     // 64B data + 16B pad per 32-k row
#define MATB (128 * ROWB)           // 10240 bytes per matrix per stage
#define STAGE_BYTES (2 * MATB)      // A, B
#define NSTAGE 4
#define GEMM_SMEM (NSTAGE * STAGE_BYTES)   // 81920

// ---------------------------------------------------------------------------
// Scratch (device globals: allocation-free per harness rules)
// ---------------------------------------------------------------------------
__device__ float g_q [ROWS*HID];
__device__ float g_k [ROWS*HID];
__device__ float g_v [ROWS*HID];
__device__ float g_sk[ROWS*HID];
__device__ float g_sv[ROWS*HID];
__device__ float g_x [ROWS*HID];
__device__ float g_sortout[BS*NB*NB];
__device__ float g_perm   [BS*NB*NB];

__device__ __half g_a16[ROWS*DM];    // inputs_q fp16
__device__ __half g_x16[ROWS*HID];   // attention output fp16
__device__ __half g_wq16[HID*DM];    // transposed [n][k]
__device__ __half g_wk16[HID*DM];
__device__ __half g_wv16[HID*DM];
__device__ __half g_wo16[DM*HID];

// ---------------------------------------------------------------------------
// PTX helpers (base-target-safe: cp.async / ldmatrix / mma.sync only)
// ---------------------------------------------------------------------------
__device__ __forceinline__ void cp16(uint32_t s, const void* g) {
    asm volatile("cp.async.cg.shared.global [%0], [%1], 16;" :: "r"(s), "l"(g));
}
#define CP_COMMIT() asm volatile("cp.async.commit_group;" ::: "memory")
#define CP_WAIT(n)  asm volatile("cp.async.wait_group %0;" :: "n"(n) : "memory")

__device__ __forceinline__ void ldsm4(uint32_t* r, uint32_t addr) {
    asm volatile("ldmatrix.sync.aligned.m8n8.x4.shared.b16 {%0,%1,%2,%3}, [%4];"
                 : "=r"(r[0]), "=r"(r[1]), "=r"(r[2]), "=r"(r[3]) : "r"(addr));
}
__device__ __forceinline__ void mma16816(float* c, const uint32_t* a,
                                         uint32_t b0, uint32_t b1) {
    asm volatile("mma.sync.aligned.m16n8k16.row.col.f32.f16.f16.f32 "
                 "{%0,%1,%2,%3}, {%4,%5,%6,%7}, {%8,%9}, {%0,%1,%2,%3};"
                 : "+f"(c[0]), "+f"(c[1]), "+f"(c[2]), "+f"(c[3])
                 : "r"(a[0]), "r"(a[1]), "r"(a[2]), "r"(a[3]), "r"(b0), "r"(b1));
}

// ---------------------------------------------------------------------------
// Convert fp32 -> fp16
// ---------------------------------------------------------------------------
__global__ __launch_bounds__(256)
void to_half(const float* __restrict__ src, __half* __restrict__ dst, int n4) {
    int i = blockIdx.x * 256 + threadIdx.x;
    if (i >= n4) return;
    float4 f = ((const float4*)src)[i];
    __half2 h0, h1;
    h0.x = __float2half_rn(f.x); h0.y = __float2half_rn(f.y);
    h1.x = __float2half_rn(f.z); h1.y = __float2half_rn(f.w);
    ((__half2*)dst)[i*2]   = h0;
    ((__half2*)dst)[i*2+1] = h1;
}

// ---------------------------------------------------------------------------
// Transpose 1024x1024 fp32 W[k][n] -> fp16 Wt[n][k]
// ---------------------------------------------------------------------------
__global__ __launch_bounds__(256)
void transpose_half(const float* __restrict__ W, __half* __restrict__ T) {
    __shared__ float t[32][33];
    const int tx = threadIdx.x, ty = threadIdx.y;
    const int x = blockIdx.x * 32 + tx;
    const int y0 = blockIdx.y * 32;
    #pragma unroll
    for (int i = ty; i < 32; i += 8) t[i][tx] = W[(size_t)(y0 + i) * 1024 + x];
    __syncthreads();
    const int k = y0 + tx;
    #pragma unroll
    for (int i = ty; i < 32; i += 8) {
        int n = blockIdx.x * 32 + i;
        T[(size_t)n * 1024 + k] = __float2half_rn(t[tx][i]);
    }
}

// ---------------------------------------------------------------------------
// HMMA GEMM: C[M,1024] = A[M,K](fp16) * B[n][k](fp16)^T + bias, fp32 accum.
//   CTA tile 128x128, 8 warps (2M x 4N), warp tile 64x32, KC=32, 4-stage cp.async.
// ---------------------------------------------------------------------------
__global__ __launch_bounds__(256, 1)
void gemm_hmma(const __half* __restrict__ A, const __half* __restrict__ B,
               const float* __restrict__ bias, float* __restrict__ C) {
    extern __shared__ __align__(128) char smem[];
    const uint32_t sbase = (uint32_t)__cvta_generic_to_shared(smem);

    const int tid  = threadIdx.x;
    const int wid  = tid >> 5, lane = tid & 31;
    const int wm   = wid >> 2;          // 0..1  (M)
    const int wn   = wid & 3;           // 0..3  (N)
    const int bx0  = blockIdx.x * TN;
    const int by0  = blockIdx.y * TM;

    // cp.async mapping: thread t loads rows (t>>2) and (t>>2)+64, 16B chunk t&3
    const int rr  = tid >> 2;
    const int c16 = tid & 3;

    auto load_stage = [&](int c, int s) {
        const uint32_t st = sbase + (uint32_t)s * STAGE_BYTES;
        const size_t kof = (size_t)c * KC + c16 * 8;
        #pragma unroll
        for (int i = 0; i < 2; i++) {
            const int row = rr + i * 64;
            const uint32_t so = (uint32_t)(row * ROWB + c16 * 16);
            cp16(st +        so, A + (size_t)(by0 + row) * DM + kof);
            cp16(st + MATB + so, B + (size_t)(bx0 + row) * DM + kof);
        }
    };

    // ldmatrix per-lane address components
    const int mi   = lane >> 3;
    const int lrow = lane & 7;
    const uint32_t aoff = (uint32_t)(((mi & 1) * 8 + lrow) * ROWB + (mi >> 1) * 16);
    const uint32_t boff = (uint32_t)(((mi >> 1) * 8 + lrow) * ROWB + (mi & 1) * 16);

    float acc[16][4];
    #pragma unroll
    for (int i = 0; i < 16; i++)
        #pragma unroll
        for (int j = 0; j < 4; j++) acc[i][j] = 0.f;

    load_stage(0, 0); CP_COMMIT();
    load_stage(1, 1); CP_COMMIT();
    load_stage(2, 2); CP_COMMIT();

    for (int c = 0; c < NCHUNK; c++) {
        if (c + 3 < NCHUNK) load_stage(c + 3, (c + 3) % NSTAGE);
        CP_COMMIT();
        CP_WAIT(3);
        __syncthreads();

        const uint32_t st = sbase + (uint32_t)(c % NSTAGE) * STAGE_BYTES;
        const uint32_t sA = st, sB = st + MATB;

        #pragma unroll
        for (int ks = 0; ks < 2; ks++) {
            const uint32_t kb = ks * 32;
            uint32_t a[4][4], b[2][4];
            #pragma unroll
            for (int mt = 0; mt < 4; mt++)
                ldsm4(a[mt], sA + (uint32_t)((wm * 64 + mt * 16) * ROWB) + kb + aoff);
            #pragma unroll
            for (int nt2 = 0; nt2 < 2; nt2++)
                ldsm4(b[nt2], sB + (uint32_t)((wn * 32 + nt2 * 16) * ROWB) + kb + boff);
            #pragma unroll
            for (int mt = 0; mt < 4; mt++)
                #pragma unroll
                for (int nt = 0; nt < 4; nt++) {
                    const int p = nt >> 1, q = (nt & 1) * 2;
                    mma16816(acc[mt*4+nt], a[mt], b[p][q], b[p][q+1]);
                }
        }
        __syncthreads();
    }

    // Epilogue
    const int g = lane >> 2, t2 = (lane & 3) * 2;
    #pragma unroll
    for (int mt = 0; mt < 4; mt++) {
        const int row0 = by0 + wm * 64 + mt * 16 + g;
        #pragma unroll
        for (int nt = 0; nt < 4; nt++) {
            const int col = bx0 + wn * 32 + nt * 8 + t2;
            const float2 bv = *(const float2*)(bias + col);
            float2 o0, o1;
            o0.x = acc[mt*4+nt][0] + bv.x; o0.y = acc[mt*4+nt][1] + bv.y;
            o1.x = acc[mt*4+nt][2] + bv.x; o1.y = acc[mt*4+nt][3] + bv.y;
            *(float2*)(C + (size_t)row0 * HID + col)       = o0;
            *(float2*)(C + (size_t)(row0 + 8) * HID + col) = o1;
        }
    }
}

// ---------------------------------------------------------------------------
// sum_key + sort logits
// ---------------------------------------------------------------------------
__global__ __launch_bounds__(256)
void sumkey_sort(const float* __restrict__ w_sort, const float* __restrict__ b_sort) {
    __shared__ float sk[HID];
    const int bn = blockIdx.x;
    const int b = bn >> 5, n = bn & 31;
    const int t = threadIdx.x;

    const float* base = g_k + ((size_t)(b * SEQ + n * BLKS)) * HID;
    for (int c = t; c < HID; c += 256) {
        float s = 0.f;
        for (int r = 0; r < BLKS; r++) s += base[(size_t)r * HID + c];
        sk[c] = s;
    }
    __syncthreads();

    const int warp = t >> 5, lane = t & 31;
    for (int m = warp; m < NB; m += 8) {
        float s = 0.f;
        for (int c = lane; c < HID; c += 32) s += sk[c] * w_sort[c * NB + m];
        #pragma unroll
        for (int o = 16; o; o >>= 1) s += __shfl_xor_sync(0xffffffffu, s, o);
        if (lane == 0) g_sortout[b * (NB*NB) + n * NB + m] = s + b_sort[m];
    }
}

// ---------------------------------------------------------------------------
// Sinkhorn
// ---------------------------------------------------------------------------
__global__ void sinkhorn_kernel() {
    __shared__ float la[32][33];
    __shared__ float colLse[32];
    const int b = blockIdx.x;
    const int j = threadIdx.x, i = threadIdx.y;

    float v = g_sortout[b * (NB*NB) + i * NB + j];

    for (int it = 0; it < 5; it++) {
        float mx = v;
        #pragma unroll
        for (int o = 16; o; o >>= 1) mx = fmaxf(mx, __shfl_xor_sync(0xffffffffu, mx, o));
        float sum = expf(v - mx);
        #pragma unroll
        for (int o = 16; o; o >>= 1) sum += __shfl_xor_sync(0xffffffffu, sum, o);
        v -= mx + logf(sum);

        la[i][j] = v;
        __syncthreads();

        float cv = la[j][i];
        float cm = cv;
        #pragma unroll
        for (int o = 16; o; o >>= 1) cm = fmaxf(cm, __shfl_xor_sync(0xffffffffu, cm, o));
        float cs = expf(cv - cm);
        #pragma unroll
        for (int o = 16; o; o >>= 1) cs += __shfl_xor_sync(0xffffffffu, cs, o);
        if (j == 0) colLse[i] = cm + logf(cs);
        __syncthreads();

        v -= colLse[j];
        __syncthreads();
    }
    g_perm[b * (NB*NB) + i * NB + j] = expf(fminf(fmaxf(v, -1.f), 1.f));
}

// ---------------------------------------------------------------------------
// blockmix
// ---------------------------------------------------------------------------
__global__ __launch_bounds__(256)
void blockmix() {
    __shared__ float p[NB][NB];
    const int b = blockIdx.y;
    const int which = blockIdx.z;
    const float* __restrict__ src = which ? g_v : g_k;
    float* __restrict__ dst = which ? g_sv : g_sk;

    const int t = threadIdx.x;
    for (int i = t; i < NB * NB; i += 256) p[i / NB][i % NB] = g_perm[b * (NB*NB) + i];
    __syncthreads();

    const size_t base = (size_t)b * PERB + (size_t)blockIdx.x * 1024;

    float acc[NB * 4];
    #pragma unroll
    for (int i = 0; i < NB * 4; i++) acc[i] = 0.f;

    for (int m = 0; m < NB; m++) {
        float kv[4];
        #pragma unroll
        for (int jj = 0; jj < 4; jj++)
            kv[jj] = src[base + (size_t)m * PERBLK + t + 256 * jj];
        #pragma unroll
        for (int n = 0; n < NB; n++) {
            float pm = p[n][m];
            #pragma unroll
            for (int jj = 0; jj < 4; jj++) acc[n * 4 + jj] += pm * kv[jj];
        }
    }

    #pragma unroll
    for (int n = 0; n < NB; n++)
        #pragma unroll
        for (int jj = 0; jj < 4; jj++)
            dst[base + (size_t)n * PERBLK + t + 256 * jj] = acc[n * 4 + jj];
}

// ---------------------------------------------------------------------------
// Block attention (fp32, online softmax)
// ---------------------------------------------------------------------------
__global__ __launch_bounds__(128)
void attn_kernel() {
    __shared__ __align__(16) float Ks[32][64];
    __shared__ __align__(16) float Vs[32][64];
    __shared__ float Ss[32][128];

    const int h = blockIdx.x, n = blockIdx.y, b = blockIdx.z;
    const int t = threadIdx.x;
    const float scale = 0.125f;

    const size_t qbase = ((size_t)(b * SEQ + n * BLKS + t)) * HID + h * HD;
    float qr[HD];
    #pragma unroll
    for (int d = 0; d < HD; d += 4) {
        float4 f = *(const float4*)(g_q + qbase + d);
        qr[d]   = f.x * scale; qr[d+1] = f.y * scale;
        qr[d+2] = f.z * scale; qr[d+3] = f.w * scale;
    }

    float o[HD];
    #pragma unroll
    for (int d = 0; d < HD; d++) o[d] = 0.f;
    float mrun = -1e30f, lrun = 0.f;

    const int r  = t >> 2;
    const int q4 = (t & 3) * 16;

    for (int kc = 0; kc < 8; kc++) {
        const int jg = kc * 32 + r;
        const float *kp, *vp;
        if (jg < BLKS) {
            size_t off = ((size_t)(b * SEQ + n * BLKS + jg)) * HID + h * HD + q4;
            kp = g_k + off; vp = g_v + off;
        } else {
            size_t off = (size_t)b * PERB + (size_t)n * PERBLK
                       + (size_t)(jg - BLKS) * HID + h * HD + q4;
            kp = g_sk + off; vp = g_sv + off;
        }
        #pragma unroll
        for (int uu = 0; uu < 4; uu++) {
            *(float4*)&Ks[r][q4 + uu * 4] = *(const float4*)(kp + uu * 4);
            *(float4*)&Vs[r][q4 + uu * 4] = *(const float4*)(vp + uu * 4);
        }
        __syncthreads();

        float cmax = -1e30f;
        #pragma unroll 4
        for (int j = 0; j < 32; j++) {
            float acc = 0.f;
            #pragma unroll
            for (int d = 0; d < HD; d += 4) {
                float4 kk = *(const float4*)&Ks[j][d];
                acc += qr[d] * kk.x + qr[d+1] * kk.y + qr[d+2] * kk.z + qr[d+3] * kk.w;
            }
            Ss[j][t] = acc;
            cmax = fmaxf(cmax, acc);
        }

        float nm   = fmaxf(mrun, cmax);
        float corr = __expf(mrun - nm);
        lrun *= corr;
        #pragma unroll
        for (int d = 0; d < HD; d++) o[d] *= corr;

        #pragma unroll 4
        for (int j = 0; j < 32; j++) {
            float pw = __expf(Ss[j][t] - nm);
            lrun += pw;
            #pragma unroll
            for (int d = 0; d < HD; d += 4) {
                float4 vv = *(const float4*)&Vs[j][d];
                o[d]   += pw * vv.x; o[d+1] += pw * vv.y;
                o[d+2] += pw * vv.z; o[d+3] += pw * vv.w;
            }
        }
        mrun = nm;
        __syncthreads();
    }

    const float inv = 1.f / lrun;
    #pragma unroll
    for (int d = 0; d < HD; d += 4) {
        float4 f;
        f.x = o[d] * inv; f.y = o[d+1] * inv;
        f.z = o[d+2] * inv; f.w = o[d+3] * inv;
        *(float4*)(g_x + qbase + d) = f;
    }
}

// ---------------------------------------------------------------------------
// Host launcher
// ---------------------------------------------------------------------------
extern "C" void kernel_launch(void* const* d_in, const int* in_sizes, int n_in,
                              void* d_out, int out_size) {
    const float* inputs_q = (const float*)d_in[0];
    const float* wq = (const float*)d_in[1];
    const float* bq = (const float*)d_in[2];
    const float* wk = (const float*)d_in[3];
    const float* bk = (const float*)d_in[4];
    const float* wv = (const float*)d_in[5];
    const float* bv = (const float*)d_in[6];
    const float* w_sort = (const float*)d_in[7];
    const float* b_sort = (const float*)d_in[8];
    const float* wo = (const float*)d_in[9];
    const float* bo = (const float*)d_in[10];
    float* out = (float*)d_out;

    float *pq, *pk, *pv, *px;
    cudaGetSymbolAddress((void**)&pq, g_q);
    cudaGetSymbolAddress((void**)&pk, g_k);
    cudaGetSymbolAddress((void**)&pv, g_v);
    cudaGetSymbolAddress((void**)&px, g_x);
    __half *a16, *x16, *wq16, *wk16, *wv16, *wo16;
    cudaGetSymbolAddress((void**)&a16,  g_a16);
    cudaGetSymbolAddress((void**)&x16,  g_x16);
    cudaGetSymbolAddress((void**)&wq16, g_wq16);
    cudaGetSymbolAddress((void**)&wk16, g_wk16);
    cudaGetSymbolAddress((void**)&wv16, g_wv16);
    cudaGetSymbolAddress((void**)&wo16, g_wo16);

    cudaFuncSetAttribute(gemm_hmma, cudaFuncAttributeMaxDynamicSharedMemorySize, GEMM_SMEM);

    const int n4 = ROWS * DM / 4;
    to_half<<<(n4 + 255) / 256, 256>>>(inputs_q, a16, n4);
    dim3 tg(32, 32);
    transpose_half<<<tg, dim3(32, 8)>>>(wq, wq16);
    transpose_half<<<tg, dim3(32, 8)>>>(wk, wk16);
    transpose_half<<<tg, dim3(32, 8)>>>(wv, wv16);
    transpose_half<<<tg, dim3(32, 8)>>>(wo, wo16);

    dim3 gg(HID / TN, ROWS / TM);
    gemm_hmma<<<gg, 256, GEMM_SMEM>>>(a16, wq16, bq, pq);
    gemm_hmma<<<gg, 256, GEMM_SMEM>>>(a16, wk16, bk, pk);
    gemm_hmma<<<gg, 256, GEMM_SMEM>>>(a16, wv16, bv, pv);

    sumkey_sort<<<BS * NB, 256>>>(w_sort, b_sort);
    sinkhorn_kernel<<<BS, dim3(32, 32)>>>();
    blockmix<<<dim3(PERBLK / 1024, BS, 2), 256>>>();
    attn_kernel<<<dim3(NH, NB, BS), 128>>>();

    to_half<<<(n4 + 255) / 256, 256>>>(px, x16, n4);
    gemm_hmma<<<gg, 256, GEMM_SMEM>>>(x16, wo16, bo, out);
}

// round 7
// speedup vs baseline: 4.4403x; 1.6649x over previous
#include <cuda_runtime.h>
#include <cuda_fp16.h>
#include <cstdint>

// ---------------------------------------------------------------------------
// SinkhornAttention: BS=4, SEQ=4096, DM=1024, H=16, HD=64, BLK=128, NB=32
// ---------------------------------------------------------------------------
#define BS   4
#define SEQ  4096
#define DM   1024
#define NH   16
#define HD   64
#define BLKS 128
#define NB   32
#define ROWS (BS*SEQ)            // 16384
#define HID  (NH*HD)             // 1024
#define PERB (SEQ*HID)           // 4194304 (elements per batch)
#define PERBLK (BLKS*HID)        // 131072

// GEMM tiling
#define TM 128
#define TN 128
#define KC 32
#define NCHUNK (DM / KC)            // 32
#define ROWB 80                     // 64B data + 16B pad per 32-k row
#define MATB (128 * ROWB)
#define STAGE_BYTES (2 * MATB)
#define NSTAGE 4
#define GEMM_SMEM (NSTAGE * STAGE_BYTES)   // 81920

// Attention smem: Q 16KB @0, K 32KB @16384, V 32KB @49152
#define ATT_SMEM 81920

// ---------------------------------------------------------------------------
// Scratch (device globals: allocation-free per harness rules)
// ---------------------------------------------------------------------------
__device__ float g_sortout[BS*NB*NB];
__device__ float g_perm   [BS*NB*NB];

__device__ __half g_a16[ROWS*DM];    // inputs_q fp16
__device__ __half g_q16[ROWS*HID];
__device__ __half g_k16[ROWS*HID];
__device__ __half g_v16[ROWS*HID];
__device__ __half g_sk16[ROWS*HID];
__device__ __half g_sv16[ROWS*HID];
__device__ __half g_x16[ROWS*HID];
__device__ __half g_wq16[HID*DM];    // transposed [n][k]
__device__ __half g_wk16[HID*DM];
__device__ __half g_wv16[HID*DM];
__device__ __half g_wo16[DM*HID];

// ---------------------------------------------------------------------------
// PTX helpers (base-target-safe: cp.async / ldmatrix / mma.sync only)
// ---------------------------------------------------------------------------
__device__ __forceinline__ void cp16(uint32_t s, const void* g) {
    asm volatile("cp.async.cg.shared.global [%0], [%1], 16;" :: "r"(s), "l"(g));
}
#define CP_COMMIT() asm volatile("cp.async.commit_group;" ::: "memory")
#define CP_WAIT(n)  asm volatile("cp.async.wait_group %0;" :: "n"(n) : "memory")

__device__ __forceinline__ void ldsm4(uint32_t* r, uint32_t addr) {
    asm volatile("ldmatrix.sync.aligned.m8n8.x4.shared.b16 {%0,%1,%2,%3}, [%4];"
                 : "=r"(r[0]), "=r"(r[1]), "=r"(r[2]), "=r"(r[3]) : "r"(addr));
}
__device__ __forceinline__ void ldsm4t(uint32_t* r, uint32_t addr) {
    asm volatile("ldmatrix.sync.aligned.m8n8.x4.trans.shared.b16 {%0,%1,%2,%3}, [%4];"
                 : "=r"(r[0]), "=r"(r[1]), "=r"(r[2]), "=r"(r[3]) : "r"(addr));
}
__device__ __forceinline__ void mma16816(float* c, const uint32_t* a,
                                         uint32_t b0, uint32_t b1) {
    asm volatile("mma.sync.aligned.m16n8k16.row.col.f32.f16.f16.f32 "
                 "{%0,%1,%2,%3}, {%4,%5,%6,%7}, {%8,%9}, {%0,%1,%2,%3};"
                 : "+f"(c[0]), "+f"(c[1]), "+f"(c[2]), "+f"(c[3])
                 : "r"(a[0]), "r"(a[1]), "r"(a[2]), "r"(a[3]), "r"(b0), "r"(b1));
}
__device__ __forceinline__ uint32_t packh2(float a, float b) {
    __half2 h = __floats2half2_rn(a, b);
    return *(uint32_t*)&h;
}

// ---------------------------------------------------------------------------
// Convert fp32 -> fp16
// ---------------------------------------------------------------------------
__global__ __launch_bounds__(256)
void to_half(const float* __restrict__ src, __half* __restrict__ dst, int n4) {
    int i = blockIdx.x * 256 + threadIdx.x;
    if (i >= n4) return;
    float4 f = ((const float4*)src)[i];
    __half2 h0, h1;
    h0.x = __float2half_rn(f.x); h0.y = __float2half_rn(f.y);
    h1.x = __float2half_rn(f.z); h1.y = __float2half_rn(f.w);
    ((__half2*)dst)[i*2]   = h0;
    ((__half2*)dst)[i*2+1] = h1;
}

// ---------------------------------------------------------------------------
// Transpose 1024x1024 fp32 W[k][n] -> fp16 Wt[n][k]
// ---------------------------------------------------------------------------
__global__ __launch_bounds__(256)
void transpose_half(const float* __restrict__ W, __half* __restrict__ T) {
    __shared__ float t[32][33];
    const int tx = threadIdx.x, ty = threadIdx.y;
    const int x = blockIdx.x * 32 + tx;
    const int y0 = blockIdx.y * 32;
    #pragma unroll
    for (int i = ty; i < 32; i += 8) t[i][tx] = W[(size_t)(y0 + i) * 1024 + x];
    __syncthreads();
    const int k = y0 + tx;
    #pragma unroll
    for (int i = ty; i < 32; i += 8) {
        int n = blockIdx.x * 32 + i;
        T[(size_t)n * 1024 + k] = __float2half_rn(t[tx][i]);
    }
}

// ---------------------------------------------------------------------------
// HMMA GEMM: C = A[M,K](fp16) * B[n][k](fp16)^T + bias, fp32 accum.
// Writes fp32 (Cf) and/or fp16 (Ch) outputs.
// ---------------------------------------------------------------------------
__global__ __launch_bounds__(256, 1)
void gemm_hmma(const __half* __restrict__ A, const __half* __restrict__ B,
               const float* __restrict__ bias,
               float* __restrict__ Cf, __half* __restrict__ Ch) {
    extern __shared__ __align__(128) char smem[];
    const uint32_t sbase = (uint32_t)__cvta_generic_to_shared(smem);

    const int tid  = threadIdx.x;
    const int wid  = tid >> 5, lane = tid & 31;
    const int wm   = wid >> 2;
    const int wn   = wid & 3;
    const int bx0  = blockIdx.x * TN;
    const int by0  = blockIdx.y * TM;

    const int rr  = tid >> 2;
    const int c16 = tid & 3;

    auto load_stage = [&](int c, int s) {
        const uint32_t st = sbase + (uint32_t)s * STAGE_BYTES;
        const size_t kof = (size_t)c * KC + c16 * 8;
        #pragma unroll
        for (int i = 0; i < 2; i++) {
            const int row = rr + i * 64;
            const uint32_t so = (uint32_t)(row * ROWB + c16 * 16);
            cp16(st +        so, A + (size_t)(by0 + row) * DM + kof);
            cp16(st + MATB + so, B + (size_t)(bx0 + row) * DM + kof);
        }
    };

    const int mi   = lane >> 3;
    const int lrow = lane & 7;
    const uint32_t aoff = (uint32_t)(((mi & 1) * 8 + lrow) * ROWB + (mi >> 1) * 16);
    const uint32_t boff = (uint32_t)(((mi >> 1) * 8 + lrow) * ROWB + (mi & 1) * 16);

    float acc[16][4];
    #pragma unroll
    for (int i = 0; i < 16; i++)
        #pragma unroll
        for (int j = 0; j < 4; j++) acc[i][j] = 0.f;

    load_stage(0, 0); CP_COMMIT();
    load_stage(1, 1); CP_COMMIT();
    load_stage(2, 2); CP_COMMIT();

    for (int c = 0; c < NCHUNK; c++) {
        if (c + 3 < NCHUNK) load_stage(c + 3, (c + 3) % NSTAGE);
        CP_COMMIT();
        CP_WAIT(3);
        __syncthreads();

        const uint32_t st = sbase + (uint32_t)(c % NSTAGE) * STAGE_BYTES;
        const uint32_t sA = st, sB = st + MATB;

        #pragma unroll
        for (int ks = 0; ks < 2; ks++) {
            const uint32_t kb = ks * 32;
            uint32_t a[4][4], b[2][4];
            #pragma unroll
            for (int mt = 0; mt < 4; mt++)
                ldsm4(a[mt], sA + (uint32_t)((wm * 64 + mt * 16) * ROWB) + kb + aoff);
            #pragma unroll
            for (int nt2 = 0; nt2 < 2; nt2++)
                ldsm4(b[nt2], sB + (uint32_t)((wn * 32 + nt2 * 16) * ROWB) + kb + boff);
            #pragma unroll
            for (int mt = 0; mt < 4; mt++)
                #pragma unroll
                for (int nt = 0; nt < 4; nt++) {
                    const int p = nt >> 1, q = (nt & 1) * 2;
                    mma16816(acc[mt*4+nt], a[mt], b[p][q], b[p][q+1]);
                }
        }
        __syncthreads();
    }

    const int g = lane >> 2, t2 = (lane & 3) * 2;
    #pragma unroll
    for (int mt = 0; mt < 4; mt++) {
        const int row0 = by0 + wm * 64 + mt * 16 + g;
        #pragma unroll
        for (int nt = 0; nt < 4; nt++) {
            const int col = bx0 + wn * 32 + nt * 8 + t2;
            const float2 bv = *(const float2*)(bias + col);
            float o00 = acc[mt*4+nt][0] + bv.x, o01 = acc[mt*4+nt][1] + bv.y;
            float o10 = acc[mt*4+nt][2] + bv.x, o11 = acc[mt*4+nt][3] + bv.y;
            if (Cf) {
                *(float2*)(Cf + (size_t)row0 * HID + col)       = make_float2(o00, o01);
                *(float2*)(Cf + (size_t)(row0 + 8) * HID + col) = make_float2(o10, o11);
            }
            if (Ch) {
                *(uint32_t*)(Ch + (size_t)row0 * HID + col)       = packh2(o00, o01);
                *(uint32_t*)(Ch + (size_t)(row0 + 8) * HID + col) = packh2(o10, o11);
            }
        }
    }
}

// ---------------------------------------------------------------------------
// sum_key + sort logits (reads fp16 K)
// ---------------------------------------------------------------------------
__global__ __launch_bounds__(256)
void sumkey_sort(const float* __restrict__ w_sort, const float* __restrict__ b_sort) {
    __shared__ float sk[HID];
    const int bn = blockIdx.x;
    const int b = bn >> 5, n = bn & 31;
    const int t = threadIdx.x;

    const __half* base = g_k16 + ((size_t)(b * SEQ + n * BLKS)) * HID;
    for (int c = t; c < HID; c += 256) {
        float s = 0.f;
        for (int r = 0; r < BLKS; r++) s += __half2float(base[(size_t)r * HID + c]);
        sk[c] = s;
    }
    __syncthreads();

    const int warp = t >> 5, lane = t & 31;
    for (int m = warp; m < NB; m += 8) {
        float s = 0.f;
        for (int c = lane; c < HID; c += 32) s += sk[c] * w_sort[c * NB + m];
        #pragma unroll
        for (int o = 16; o; o >>= 1) s += __shfl_xor_sync(0xffffffffu, s, o);
        if (lane == 0) g_sortout[b * (NB*NB) + n * NB + m] = s + b_sort[m];
    }
}

// ---------------------------------------------------------------------------
// Sinkhorn
// ---------------------------------------------------------------------------
__global__ void sinkhorn_kernel() {
    __shared__ float la[32][33];
    __shared__ float colLse[32];
    const int b = blockIdx.x;
    const int j = threadIdx.x, i = threadIdx.y;

    float v = g_sortout[b * (NB*NB) + i * NB + j];

    for (int it = 0; it < 5; it++) {
        float mx = v;
        #pragma unroll
        for (int o = 16; o; o >>= 1) mx = fmaxf(mx, __shfl_xor_sync(0xffffffffu, mx, o));
        float sum = expf(v - mx);
        #pragma unroll
        for (int o = 16; o; o >>= 1) sum += __shfl_xor_sync(0xffffffffu, sum, o);
        v -= mx + logf(sum);

        la[i][j] = v;
        __syncthreads();

        float cv = la[j][i];
        float cm = cv;
        #pragma unroll
        for (int o = 16; o; o >>= 1) cm = fmaxf(cm, __shfl_xor_sync(0xffffffffu, cm, o));
        float cs = expf(cv - cm);
        #pragma unroll
        for (int o = 16; o; o >>= 1) cs += __shfl_xor_sync(0xffffffffu, cs, o);
        if (j == 0) colLse[i] = cm + logf(cs);
        __syncthreads();

        v -= colLse[j];
        __syncthreads();
    }
    g_perm[b * (NB*NB) + i * NB + j] = expf(fminf(fmaxf(v, -1.f), 1.f));
}

// ---------------------------------------------------------------------------
// blockmix (fp16 in/out, fp32 accumulate)
// ---------------------------------------------------------------------------
__global__ __launch_bounds__(256)
void blockmix() {
    __shared__ float p[NB][NB];
    const int b = blockIdx.y;
    const int which = blockIdx.z;
    const __half2* __restrict__ src = (const __half2*)(which ? g_v16 : g_k16);
    __half2* __restrict__ dst = (__half2*)(which ? g_sv16 : g_sk16);

    const int t = threadIdx.x;
    for (int i = t; i < NB * NB; i += 256) p[i / NB][i % NB] = g_perm[b * (NB*NB) + i];
    __syncthreads();

    const size_t base = (size_t)b * (PERB/2) + (size_t)blockIdx.x * 512;

    float2 acc[NB][2];
    #pragma unroll
    for (int i = 0; i < NB; i++) { acc[i][0] = make_float2(0.f,0.f); acc[i][1] = make_float2(0.f,0.f); }

    for (int m = 0; m < NB; m++) {
        float2 f0 = __half22float2(src[base + (size_t)m * (PERBLK/2) + t]);
        float2 f1 = __half22float2(src[base + (size_t)m * (PERBLK/2) + t + 256]);
        #pragma unroll
        for (int n = 0; n < NB; n++) {
            float pm = p[n][m];
            acc[n][0].x += pm * f0.x; acc[n][0].y += pm * f0.y;
            acc[n][1].x += pm * f1.x; acc[n][1].y += pm * f1.y;
        }
    }

    #pragma unroll
    for (int n = 0; n < NB; n++) {
        dst[base + (size_t)n * (PERBLK/2) + t]       = __floats2half2_rn(acc[n][0].x, acc[n][0].y);
        dst[base + (size_t)n * (PERBLK/2) + t + 256] = __floats2half2_rn(acc[n][1].x, acc[n][1].y);
    }
}

// ---------------------------------------------------------------------------
// Block attention, fp16 HMMA: per (h,n,b): Q[128,64] vs K/V cat [256,64].
// 8 warps x 16 Q-rows; all K/V in smem; online softmax over 4 chunks of 64.
// ---------------------------------------------------------------------------
__global__ __launch_bounds__(256, 2)
void attn_kernel() {
    extern __shared__ __align__(128) char sm[];
    const uint32_t sb = (uint32_t)__cvta_generic_to_shared(sm);
    const uint32_t sQ = sb, sK = sb + 16384, sV = sb + 49152;

    const int h = blockIdx.x, n = blockIdx.y, b = blockIdx.z;
    const int t = threadIdx.x;
    const int w = t >> 5, lane = t & 31;

    // ---- stage Q (128x64), K/V (256x64) into swizzled fp16 smem
    const __half* qg = g_q16 + ((size_t)(b * SEQ + n * BLKS)) * HID + h * HD;
    #pragma unroll
    for (int i = 0; i < 4; i++) {
        const int task = t + i * 256;
        const int row = task >> 3, ch = task & 7;
        cp16(sQ + row * 128 + (((ch ^ row) & 7) << 4), qg + (size_t)row * HID + ch * 8);
    }
    #pragma unroll
    for (int i = 0; i < 8; i++) {
        const int task = t + i * 256;
        const int row = task >> 3, ch = task & 7;
        const __half* kp = (row < BLKS)
            ? g_k16 + ((size_t)(b * SEQ + n * BLKS + row)) * HID + h * HD
            : g_sk16 + (size_t)b * PERB + (size_t)n * PERBLK + (size_t)(row - BLKS) * HID + h * HD;
        cp16(sK + row * 128 + (((ch ^ row) & 7) << 4), kp + ch * 8);
    }
    #pragma unroll
    for (int i = 0; i < 8; i++) {
        const int task = t + i * 256;
        const int row = task >> 3, ch = task & 7;
        const __half* vp = (row < BLKS)
            ? g_v16 + ((size_t)(b * SEQ + n * BLKS + row)) * HID + h * HD
            : g_sv16 + (size_t)b * PERB + (size_t)n * PERBLK + (size_t)(row - BLKS) * HID + h * HD;
        cp16(sV + row * 128 + (((ch ^ row) & 7) << 4), vp + ch * 8);
    }
    CP_COMMIT(); CP_WAIT(0);
    __syncthreads();

    const int mi = lane >> 3, lrow = lane & 7;
    const int g = lane >> 2, t2 = (lane & 3) * 2;

    // ---- preload Q fragments (4 d-ktiles)
    uint32_t qa[4][4];
    {
        const int qrow = w * 16 + (mi & 1) * 8 + lrow;
        const uint32_t qb = sQ + qrow * 128;
        const int qsw = qrow & 7;
        #pragma unroll
        for (int kt = 0; kt < 4; kt++) {
            const int ch = kt * 2 + (mi >> 1);
            ldsm4(qa[kt], qb + ((ch ^ qsw) << 4));
        }
    }

    float of[8][4];
    #pragma unroll
    for (int i = 0; i < 8; i++)
        #pragma unroll
        for (int j = 0; j < 4; j++) of[i][j] = 0.f;
    float M0 = -1e30f, M1 = -1e30f, p0 = 0.f, p1 = 0.f;

    const int krow_c = (mi >> 1) * 8 + lrow;   // K b-frag row within 16-key group
    const int vrow_c = (mi & 1) * 8 + lrow;    // V trans row within 16-key group

    for (int kc = 0; kc < 4; kc++) {
        // ---- S = Q @ K^T for 64 keys
        float sc[8][4];
        #pragma unroll
        for (int i = 0; i < 8; i++)
            #pragma unroll
            for (int j = 0; j < 4; j++) sc[i][j] = 0.f;

        #pragma unroll
        for (int kt = 0; kt < 4; kt++) {
            #pragma unroll
            for (int ng = 0; ng < 4; ng++) {
                const int krow = kc * 64 + ng * 16 + krow_c;
                const int ch = kt * 2 + (mi & 1);
                uint32_t kb[4];
                ldsm4(kb, sK + krow * 128 + (((ch ^ krow) & 7) << 4));
                mma16816(sc[ng*2],   qa[kt], kb[0], kb[1]);
                mma16816(sc[ng*2+1], qa[kt], kb[2], kb[3]);
            }
        }
        #pragma unroll
        for (int i = 0; i < 8; i++)
            #pragma unroll
            for (int j = 0; j < 4; j++) sc[i][j] *= 0.125f;

        // ---- row maxes (rows g and g+8)
        float m0 = -1e30f, m1 = -1e30f;
        #pragma unroll
        for (int i = 0; i < 8; i++) {
            m0 = fmaxf(m0, fmaxf(sc[i][0], sc[i][1]));
            m1 = fmaxf(m1, fmaxf(sc[i][2], sc[i][3]));
        }
        m0 = fmaxf(m0, __shfl_xor_sync(0xffffffffu, m0, 1));
        m0 = fmaxf(m0, __shfl_xor_sync(0xffffffffu, m0, 2));
        m1 = fmaxf(m1, __shfl_xor_sync(0xffffffffu, m1, 1));
        m1 = fmaxf(m1, __shfl_xor_sync(0xffffffffu, m1, 2));

        const float nM0 = fmaxf(M0, m0), nM1 = fmaxf(M1, m1);
        const float c0 = __expf(M0 - nM0), c1 = __expf(M1 - nM1);
        p0 *= c0; p1 *= c1;
        #pragma unroll
        for (int i = 0; i < 8; i++) {
            of[i][0] *= c0; of[i][1] *= c0;
            of[i][2] *= c1; of[i][3] *= c1;
        }
        M0 = nM0; M1 = nM1;

        // ---- P = exp(S - M), accumulate l
        #pragma unroll
        for (int i = 0; i < 8; i++) {
            sc[i][0] = __expf(sc[i][0] - M0);
            sc[i][1] = __expf(sc[i][1] - M0);
            sc[i][2] = __expf(sc[i][2] - M1);
            sc[i][3] = __expf(sc[i][3] - M1);
            p0 += sc[i][0] + sc[i][1];
            p1 += sc[i][2] + sc[i][3];
        }

        // ---- O += P @ V
        #pragma unroll
        for (int kt = 0; kt < 4; kt++) {
            uint32_t pa[4];
            pa[0] = packh2(sc[2*kt][0],   sc[2*kt][1]);
            pa[1] = packh2(sc[2*kt][2],   sc[2*kt][3]);
            pa[2] = packh2(sc[2*kt+1][0], sc[2*kt+1][1]);
            pa[3] = packh2(sc[2*kt+1][2], sc[2*kt+1][3]);
            const int vrow = kc * 64 + kt * 16 + vrow_c;
            const uint32_t vb_base = sV + vrow * 128;
            const int vsw = vrow & 7;
            #pragma unroll
            for (int dg = 0; dg < 4; dg++) {
                const int ch = dg * 2 + (mi >> 1);
                uint32_t vb[4];
                ldsm4t(vb, vb_base + ((ch ^ vsw) << 4));
                mma16816(of[dg*2],   pa, vb[0], vb[1]);
                mma16816(of[dg*2+1], pa, vb[2], vb[3]);
            }
        }
    }

    // ---- finalize
    p0 += __shfl_xor_sync(0xffffffffu, p0, 1);
    p0 += __shfl_xor_sync(0xffffffffu, p0, 2);
    p1 += __shfl_xor_sync(0xffffffffu, p1, 1);
    p1 += __shfl_xor_sync(0xffffffffu, p1, 2);
    const float i0 = 1.f / p0, i1 = 1.f / p1;

    const size_t o0 = ((size_t)(b * SEQ + n * BLKS + w * 16 + g)) * HID + h * HD;
    const size_t o1 = o0 + (size_t)8 * HID;
    #pragma unroll
    for (int dg = 0; dg < 8; dg++) {
        *(uint32_t*)(g_x16 + o0 + dg * 8 + t2) = packh2(of[dg][0] * i0, of[dg][1] * i0);
        *(uint32_t*)(g_x16 + o1 + dg * 8 + t2) = packh2(of[dg][2] * i1, of[dg][3] * i1);
    }
}

// ---------------------------------------------------------------------------
// Host launcher
// ---------------------------------------------------------------------------
extern "C" void kernel_launch(void* const* d_in, const int* in_sizes, int n_in,
                              void* d_out, int out_size) {
    const float* inputs_q = (const float*)d_in[0];
    const float* wq = (const float*)d_in[1];
    const float* bq = (const float*)d_in[2];
    const float* wk = (const float*)d_in[3];
    const float* bk = (const float*)d_in[4];
    const float* wv = (const float*)d_in[5];
    const float* bv = (const float*)d_in[6];
    const float* w_sort = (const float*)d_in[7];
    const float* b_sort = (const float*)d_in[8];
    const float* wo = (const float*)d_in[9];
    const float* bo = (const float*)d_in[10];
    float* out = (float*)d_out;

    __half *a16, *q16, *k16, *v16, *x16, *wq16, *wk16, *wv16, *wo16;
    cudaGetSymbolAddress((void**)&a16,  g_a16);
    cudaGetSymbolAddress((void**)&q16,  g_q16);
    cudaGetSymbolAddress((void**)&k16,  g_k16);
    cudaGetSymbolAddress((void**)&v16,  g_v16);
    cudaGetSymbolAddress((void**)&x16,  g_x16);
    cudaGetSymbolAddress((void**)&wq16, g_wq16);
    cudaGetSymbolAddress((void**)&wk16, g_wk16);
    cudaGetSymbolAddress((void**)&wv16, g_wv16);
    cudaGetSymbolAddress((void**)&wo16, g_wo16);

    cudaFuncSetAttribute(gemm_hmma, cudaFuncAttributeMaxDynamicSharedMemorySize, GEMM_SMEM);
    cudaFuncSetAttribute(attn_kernel, cudaFuncAttributeMaxDynamicSharedMemorySize, ATT_SMEM);

    const int n4 = ROWS * DM / 4;
    to_half<<<(n4 + 255) / 256, 256>>>(inputs_q, a16, n4);
    dim3 tg(32, 32);
    transpose_half<<<tg, dim3(32, 8)>>>(wq, wq16);
    transpose_half<<<tg, dim3(32, 8)>>>(wk, wk16);
    transpose_half<<<tg, dim3(32, 8)>>>(wv, wv16);
    transpose_half<<<tg, dim3(32, 8)>>>(wo, wo16);

    dim3 gg(HID / TN, ROWS / TM);
    gemm_hmma<<<gg, 256, GEMM_SMEM>>>(a16, wq16, bq, nullptr, q16);
    gemm_hmma<<<gg, 256, GEMM_SMEM>>>(a16, wk16, bk, nullptr, k16);
    gemm_hmma<<<gg, 256, GEMM_SMEM>>>(a16, wv16, bv, nullptr, v16);

    sumkey_sort<<<BS * NB, 256>>>(w_sort, b_sort);
    sinkhorn_kernel<<<BS, dim3(32, 32)>>>();
    blockmix<<<dim3(PERBLK / 1024, BS, 2), 256>>>();
    attn_kernel<<<dim3(NH, NB, BS), 256, ATT_SMEM>>>();

    gemm_hmma<<<gg, 256, GEMM_SMEM>>>(x16, wo16, bo, out, nullptr);
}

// round 8
// speedup vs baseline: 4.6292x; 1.0425x over previous
#include <cuda_runtime.h>
#include <cuda_fp16.h>
#include <cstdint>

// ---------------------------------------------------------------------------
// SinkhornAttention: BS=4, SEQ=4096, DM=1024, H=16, HD=64, BLK=128, NB=32
// ---------------------------------------------------------------------------
#define BS   4
#define SEQ  4096
#define DM   1024
#define NH   16
#define HD   64
#define BLKS 128
#define NB   32
#define ROWS (BS*SEQ)            // 16384
#define HID  (NH*HD)             // 1024
#define PERB (SEQ*HID)           // 4194304 (elements per batch)
#define PERBLK (BLKS*HID)        // 131072

// GEMM tiling: CTA 128x256, 8 warps (2M x 4N), warp tile 64x64
#define TM 128
#define TN 256
#define KC 32
#define NCHUNK (DM / KC)            // 32
#define ROWB 80                     // 64B data + 16B pad per 32-k row
#define MATB_A (128 * ROWB)         // 10240
#define MATB_B (256 * ROWB)         // 20480
#define STAGE_BYTES (MATB_A + MATB_B)  // 30720
#define NSTAGE 4
#define GEMM_SMEM (NSTAGE * STAGE_BYTES)   // 122880

// Attention smem: Q 16KB @0, K 32KB @16384, V 32KB @49152
#define ATT_SMEM 81920

// ---------------------------------------------------------------------------
// Scratch (device globals: allocation-free per harness rules)
// ---------------------------------------------------------------------------
__device__ float g_sortout[BS*NB*NB];
__device__ float g_perm   [BS*NB*NB];

__device__ __half g_a16[ROWS*DM];    // inputs_q fp16
__device__ __half g_q16[ROWS*HID];
__device__ __half g_k16[ROWS*HID];
__device__ __half g_v16[ROWS*HID];
__device__ __half g_sk16[ROWS*HID];
__device__ __half g_sv16[ROWS*HID];
__device__ __half g_x16[ROWS*HID];
__device__ __half g_wq16[HID*DM];    // transposed [n][k]
__device__ __half g_wk16[HID*DM];
__device__ __half g_wv16[HID*DM];
__device__ __half g_wo16[DM*HID];

// ---------------------------------------------------------------------------
// PTX helpers (base-target-safe: cp.async / ldmatrix / mma.sync only)
// ---------------------------------------------------------------------------
__device__ __forceinline__ void cp16(uint32_t s, const void* g) {
    asm volatile("cp.async.cg.shared.global [%0], [%1], 16;" :: "r"(s), "l"(g));
}
#define CP_COMMIT() asm volatile("cp.async.commit_group;" ::: "memory")
#define CP_WAIT(n)  asm volatile("cp.async.wait_group %0;" :: "n"(n) : "memory")

__device__ __forceinline__ void ldsm4(uint32_t* r, uint32_t addr) {
    asm volatile("ldmatrix.sync.aligned.m8n8.x4.shared.b16 {%0,%1,%2,%3}, [%4];"
                 : "=r"(r[0]), "=r"(r[1]), "=r"(r[2]), "=r"(r[3]) : "r"(addr));
}
__device__ __forceinline__ void ldsm4t(uint32_t* r, uint32_t addr) {
    asm volatile("ldmatrix.sync.aligned.m8n8.x4.trans.shared.b16 {%0,%1,%2,%3}, [%4];"
                 : "=r"(r[0]), "=r"(r[1]), "=r"(r[2]), "=r"(r[3]) : "r"(addr));
}
__device__ __forceinline__ void mma16816(float* c, const uint32_t* a,
                                         uint32_t b0, uint32_t b1) {
    asm volatile("mma.sync.aligned.m16n8k16.row.col.f32.f16.f16.f32 "
                 "{%0,%1,%2,%3}, {%4,%5,%6,%7}, {%8,%9}, {%0,%1,%2,%3};"
                 : "+f"(c[0]), "+f"(c[1]), "+f"(c[2]), "+f"(c[3])
                 : "r"(a[0]), "r"(a[1]), "r"(a[2]), "r"(a[3]), "r"(b0), "r"(b1));
}
__device__ __forceinline__ uint32_t packh2(float a, float b) {
    __half2 h = __floats2half2_rn(a, b);
    return *(uint32_t*)&h;
}

// ---------------------------------------------------------------------------
// Convert fp32 -> fp16
// ---------------------------------------------------------------------------
__global__ __launch_bounds__(256)
void to_half(const float* __restrict__ src, __half* __restrict__ dst, int n4) {
    int i = blockIdx.x * 256 + threadIdx.x;
    if (i >= n4) return;
    float4 f = ((const float4*)src)[i];
    __half2 h0, h1;
    h0.x = __float2half_rn(f.x); h0.y = __float2half_rn(f.y);
    h1.x = __float2half_rn(f.z); h1.y = __float2half_rn(f.w);
    ((__half2*)dst)[i*2]   = h0;
    ((__half2*)dst)[i*2+1] = h1;
}

// ---------------------------------------------------------------------------
// Transpose 4x 1024x1024 fp32 W[k][n] -> fp16 Wt[n][k], fused (grid.z selects)
// ---------------------------------------------------------------------------
__global__ __launch_bounds__(256)
void transpose_half4(const float* __restrict__ W0, const float* __restrict__ W1,
                     const float* __restrict__ W2, const float* __restrict__ W3,
                     __half* __restrict__ T0, __half* __restrict__ T1,
                     __half* __restrict__ T2, __half* __restrict__ T3) {
    const float* W = (blockIdx.z == 0) ? W0 : (blockIdx.z == 1) ? W1
                   : (blockIdx.z == 2) ? W2 : W3;
    __half* T = (blockIdx.z == 0) ? T0 : (blockIdx.z == 1) ? T1
              : (blockIdx.z == 2) ? T2 : T3;
    __shared__ float t[32][33];
    const int tx = threadIdx.x, ty = threadIdx.y;
    const int x = blockIdx.x * 32 + tx;
    const int y0 = blockIdx.y * 32;
    #pragma unroll
    for (int i = ty; i < 32; i += 8) t[i][tx] = W[(size_t)(y0 + i) * 1024 + x];
    __syncthreads();
    const int k = y0 + tx;
    #pragma unroll
    for (int i = ty; i < 32; i += 8) {
        int n = blockIdx.x * 32 + i;
        T[(size_t)n * 1024 + k] = __float2half_rn(t[tx][i]);
    }
}

// ---------------------------------------------------------------------------
// HMMA GEMM: C = A[M,K](fp16) * B[n][k](fp16)^T + bias, fp32 accum.
// CTA tile 128x256, warp tile 64x64, KC=32, 4-stage cp.async.
// Writes fp32 (Cf) or fp16 (Ch).
// ---------------------------------------------------------------------------
__global__ __launch_bounds__(256, 1)
void gemm_hmma(const __half* __restrict__ A, const __half* __restrict__ B,
               const float* __restrict__ bias,
               float* __restrict__ Cf, __half* __restrict__ Ch) {
    extern __shared__ __align__(128) char smem[];
    const uint32_t sbase = (uint32_t)__cvta_generic_to_shared(smem);

    const int tid  = threadIdx.x;
    const int wid  = tid >> 5, lane = tid & 31;
    const int wm   = wid >> 2;          // 0..1 (M half)
    const int wn   = wid & 3;           // 0..3 (N quarter)
    const int bx0  = blockIdx.x * TN;
    const int by0  = blockIdx.y * TM;

    const int rr  = tid >> 2;           // 0..63
    const int c16 = tid & 3;

    auto load_stage = [&](int c, int s) {
        const uint32_t st = sbase + (uint32_t)s * STAGE_BYTES;
        const size_t kof = (size_t)c * KC + c16 * 8;
        #pragma unroll
        for (int i = 0; i < 2; i++) {              // A: 128 rows
            const int row = rr + i * 64;
            cp16(st + (uint32_t)(row * ROWB + c16 * 16),
                 A + (size_t)(by0 + row) * DM + kof);
        }
        #pragma unroll
        for (int i = 0; i < 4; i++) {              // B: 256 rows
            const int row = rr + i * 64;
            cp16(st + MATB_A + (uint32_t)(row * ROWB + c16 * 16),
                 B + (size_t)(bx0 + row) * DM + kof);
        }
    };

    const int mi   = lane >> 3;
    const int lrow = lane & 7;
    const uint32_t aoff = (uint32_t)(((mi & 1) * 8 + lrow) * ROWB + (mi >> 1) * 16);
    const uint32_t boff = (uint32_t)(((mi >> 1) * 8 + lrow) * ROWB + (mi & 1) * 16);

    float acc[4][8][4];
    #pragma unroll
    for (int i = 0; i < 4; i++)
        #pragma unroll
        for (int j = 0; j < 8; j++)
            #pragma unroll
            for (int k = 0; k < 4; k++) acc[i][j][k] = 0.f;

    load_stage(0, 0); CP_COMMIT();
    load_stage(1, 1); CP_COMMIT();
    load_stage(2, 2); CP_COMMIT();

    for (int c = 0; c < NCHUNK; c++) {
        if (c + 3 < NCHUNK) load_stage(c + 3, (c + 3) % NSTAGE);
        CP_COMMIT();
        CP_WAIT(3);
        __syncthreads();

        const uint32_t st = sbase + (uint32_t)(c % NSTAGE) * STAGE_BYTES;
        const uint32_t sA = st, sB = st + MATB_A;

        #pragma unroll
        for (int ks = 0; ks < 2; ks++) {
            const uint32_t kb = ks * 32;
            uint32_t a[4][4], b[4][4];
            #pragma unroll
            for (int mt = 0; mt < 4; mt++)
                ldsm4(a[mt], sA + (uint32_t)((wm * 64 + mt * 16) * ROWB) + kb + aoff);
            #pragma unroll
            for (int nb = 0; nb < 4; nb++)
                ldsm4(b[nb], sB + (uint32_t)((wn * 64 + nb * 16) * ROWB) + kb + boff);
            #pragma unroll
            for (int mt = 0; mt < 4; mt++)
                #pragma unroll
                for (int nt = 0; nt < 8; nt++) {
                    const int p = nt >> 1, q = (nt & 1) * 2;
                    mma16816(acc[mt][nt], a[mt], b[p][q], b[p][q+1]);
                }
        }
        __syncthreads();
    }

    const int g = lane >> 2, t2 = (lane & 3) * 2;
    #pragma unroll
    for (int mt = 0; mt < 4; mt++) {
        const int row0 = by0 + wm * 64 + mt * 16 + g;
        #pragma unroll
        for (int nt = 0; nt < 8; nt++) {
            const int col = bx0 + wn * 64 + nt * 8 + t2;
            const float2 bv = *(const float2*)(bias + col);
            float o00 = acc[mt][nt][0] + bv.x, o01 = acc[mt][nt][1] + bv.y;
            float o10 = acc[mt][nt][2] + bv.x, o11 = acc[mt][nt][3] + bv.y;
            if (Cf) {
                *(float2*)(Cf + (size_t)row0 * HID + col)       = make_float2(o00, o01);
                *(float2*)(Cf + (size_t)(row0 + 8) * HID + col) = make_float2(o10, o11);
            }
            if (Ch) {
                *(uint32_t*)(Ch + (size_t)row0 * HID + col)       = packh2(o00, o01);
                *(uint32_t*)(Ch + (size_t)(row0 + 8) * HID + col) = packh2(o10, o11);
            }
        }
    }
}

// ---------------------------------------------------------------------------
// sum_key + sort logits (reads fp16 K)
// ---------------------------------------------------------------------------
__global__ __launch_bounds__(256)
void sumkey_sort(const float* __restrict__ w_sort, const float* __restrict__ b_sort) {
    __shared__ float sk[HID];
    const int bn = blockIdx.x;
    const int b = bn >> 5, n = bn & 31;
    const int t = threadIdx.x;

    const __half* base = g_k16 + ((size_t)(b * SEQ + n * BLKS)) * HID;
    for (int c = t; c < HID; c += 256) {
        float s = 0.f;
        for (int r = 0; r < BLKS; r++) s += __half2float(base[(size_t)r * HID + c]);
        sk[c] = s;
    }
    __syncthreads();

    const int warp = t >> 5, lane = t & 31;
    for (int m = warp; m < NB; m += 8) {
        float s = 0.f;
        for (int c = lane; c < HID; c += 32) s += sk[c] * w_sort[c * NB + m];
        #pragma unroll
        for (int o = 16; o; o >>= 1) s += __shfl_xor_sync(0xffffffffu, s, o);
        if (lane == 0) g_sortout[b * (NB*NB) + n * NB + m] = s + b_sort[m];
    }
}

// ---------------------------------------------------------------------------
// Sinkhorn
// ---------------------------------------------------------------------------
__global__ void sinkhorn_kernel() {
    __shared__ float la[32][33];
    __shared__ float colLse[32];
    const int b = blockIdx.x;
    const int j = threadIdx.x, i = threadIdx.y;

    float v = g_sortout[b * (NB*NB) + i * NB + j];

    for (int it = 0; it < 5; it++) {
        float mx = v;
        #pragma unroll
        for (int o = 16; o; o >>= 1) mx = fmaxf(mx, __shfl_xor_sync(0xffffffffu, mx, o));
        float sum = expf(v - mx);
        #pragma unroll
        for (int o = 16; o; o >>= 1) sum += __shfl_xor_sync(0xffffffffu, sum, o);
        v -= mx + logf(sum);

        la[i][j] = v;
        __syncthreads();

        float cv = la[j][i];
        float cm = cv;
        #pragma unroll
        for (int o = 16; o; o >>= 1) cm = fmaxf(cm, __shfl_xor_sync(0xffffffffu, cm, o));
        float cs = expf(cv - cm);
        #pragma unroll
        for (int o = 16; o; o >>= 1) cs += __shfl_xor_sync(0xffffffffu, cs, o);
        if (j == 0) colLse[i] = cm + logf(cs);
        __syncthreads();

        v -= colLse[j];
        __syncthreads();
    }
    g_perm[b * (NB*NB) + i * NB + j] = expf(fminf(fmaxf(v, -1.f), 1.f));
}

// ---------------------------------------------------------------------------
// blockmix (fp16 in/out, fp32 accumulate)
// ---------------------------------------------------------------------------
__global__ __launch_bounds__(256)
void blockmix() {
    __shared__ float p[NB][NB];
    const int b = blockIdx.y;
    const int which = blockIdx.z;
    const __half2* __restrict__ src = (const __half2*)(which ? g_v16 : g_k16);
    __half2* __restrict__ dst = (__half2*)(which ? g_sv16 : g_sk16);

    const int t = threadIdx.x;
    for (int i = t; i < NB * NB; i += 256) p[i / NB][i % NB] = g_perm[b * (NB*NB) + i];
    __syncthreads();

    const size_t base = (size_t)b * (PERB/2) + (size_t)blockIdx.x * 512;

    float2 acc[NB][2];
    #pragma unroll
    for (int i = 0; i < NB; i++) { acc[i][0] = make_float2(0.f,0.f); acc[i][1] = make_float2(0.f,0.f); }

    for (int m = 0; m < NB; m++) {
        float2 f0 = __half22float2(src[base + (size_t)m * (PERBLK/2) + t]);
        float2 f1 = __half22float2(src[base + (size_t)m * (PERBLK/2) + t + 256]);
        #pragma unroll
        for (int n = 0; n < NB; n++) {
            float pm = p[n][m];
            acc[n][0].x += pm * f0.x; acc[n][0].y += pm * f0.y;
            acc[n][1].x += pm * f1.x; acc[n][1].y += pm * f1.y;
        }
    }

    #pragma unroll
    for (int n = 0; n < NB; n++) {
        dst[base + (size_t)n * (PERBLK/2) + t]       = __floats2half2_rn(acc[n][0].x, acc[n][0].y);
        dst[base + (size_t)n * (PERBLK/2) + t + 256] = __floats2half2_rn(acc[n][1].x, acc[n][1].y);
    }
}

// ---------------------------------------------------------------------------
// Block attention, fp16 HMMA (unchanged from R7)
// ---------------------------------------------------------------------------
__global__ __launch_bounds__(256, 2)
void attn_kernel() {
    extern __shared__ __align__(128) char sm[];
    const uint32_t sb = (uint32_t)__cvta_generic_to_shared(sm);
    const uint32_t sQ = sb, sK = sb + 16384, sV = sb + 49152;

    const int h = blockIdx.x, n = blockIdx.y, b = blockIdx.z;
    const int t = threadIdx.x;
    const int w = t >> 5, lane = t & 31;

    const __half* qg = g_q16 + ((size_t)(b * SEQ + n * BLKS)) * HID + h * HD;
    #pragma unroll
    for (int i = 0; i < 4; i++) {
        const int task = t + i * 256;
        const int row = task >> 3, ch = task & 7;
        cp16(sQ + row * 128 + (((ch ^ row) & 7) << 4), qg + (size_t)row * HID + ch * 8);
    }
    #pragma unroll
    for (int i = 0; i < 8; i++) {
        const int task = t + i * 256;
        const int row = task >> 3, ch = task & 7;
        const __half* kp = (row < BLKS)
            ? g_k16 + ((size_t)(b * SEQ + n * BLKS + row)) * HID + h * HD
            : g_sk16 + (size_t)b * PERB + (size_t)n * PERBLK + (size_t)(row - BLKS) * HID + h * HD;
        cp16(sK + row * 128 + (((ch ^ row) & 7) << 4), kp + ch * 8);
    }
    #pragma unroll
    for (int i = 0; i < 8; i++) {
        const int task = t + i * 256;
        const int row = task >> 3, ch = task & 7;
        const __half* vp = (row < BLKS)
            ? g_v16 + ((size_t)(b * SEQ + n * BLKS + row)) * HID + h * HD
            : g_sv16 + (size_t)b * PERB + (size_t)n * PERBLK + (size_t)(row - BLKS) * HID + h * HD;
        cp16(sV + row * 128 + (((ch ^ row) & 7) << 4), vp + ch * 8);
    }
    CP_COMMIT(); CP_WAIT(0);
    __syncthreads();

    const int mi = lane >> 3, lrow = lane & 7;
    const int g = lane >> 2, t2 = (lane & 3) * 2;

    uint32_t qa[4][4];
    {
        const int qrow = w * 16 + (mi & 1) * 8 + lrow;
        const uint32_t qb = sQ + qrow * 128;
        const int qsw = qrow & 7;
        #pragma unroll
        for (int kt = 0; kt < 4; kt++) {
            const int ch = kt * 2 + (mi >> 1);
            ldsm4(qa[kt], qb + ((ch ^ qsw) << 4));
        }
    }

    float of[8][4];
    #pragma unroll
    for (int i = 0; i < 8; i++)
        #pragma unroll
        for (int j = 0; j < 4; j++) of[i][j] = 0.f;
    float M0 = -1e30f, M1 = -1e30f, p0 = 0.f, p1 = 0.f;

    const int krow_c = (mi >> 1) * 8 + lrow;
    const int vrow_c = (mi & 1) * 8 + lrow;

    for (int kc = 0; kc < 4; kc++) {
        float sc[8][4];
        #pragma unroll
        for (int i = 0; i < 8; i++)
            #pragma unroll
            for (int j = 0; j < 4; j++) sc[i][j] = 0.f;

        #pragma unroll
        for (int kt = 0; kt < 4; kt++) {
            #pragma unroll
            for (int ng = 0; ng < 4; ng++) {
                const int krow = kc * 64 + ng * 16 + krow_c;
                const int ch = kt * 2 + (mi & 1);
                uint32_t kb[4];
                ldsm4(kb, sK + krow * 128 + (((ch ^ krow) & 7) << 4));
                mma16816(sc[ng*2],   qa[kt], kb[0], kb[1]);
                mma16816(sc[ng*2+1], qa[kt], kb[2], kb[3]);
            }
        }
        #pragma unroll
        for (int i = 0; i < 8; i++)
            #pragma unroll
            for (int j = 0; j < 4; j++) sc[i][j] *= 0.125f;

        float m0 = -1e30f, m1 = -1e30f;
        #pragma unroll
        for (int i = 0; i < 8; i++) {
            m0 = fmaxf(m0, fmaxf(sc[i][0], sc[i][1]));
            m1 = fmaxf(m1, fmaxf(sc[i][2], sc[i][3]));
        }
        m0 = fmaxf(m0, __shfl_xor_sync(0xffffffffu, m0, 1));
        m0 = fmaxf(m0, __shfl_xor_sync(0xffffffffu, m0, 2));
        m1 = fmaxf(m1, __shfl_xor_sync(0xffffffffu, m1, 1));
        m1 = fmaxf(m1, __shfl_xor_sync(0xffffffffu, m1, 2));

        const float nM0 = fmaxf(M0, m0), nM1 = fmaxf(M1, m1);
        const float c0 = __expf(M0 - nM0), c1 = __expf(M1 - nM1);
        p0 *= c0; p1 *= c1;
        #pragma unroll
        for (int i = 0; i < 8; i++) {
            of[i][0] *= c0; of[i][1] *= c0;
            of[i][2] *= c1; of[i][3] *= c1;
        }
        M0 = nM0; M1 = nM1;

        #pragma unroll
        for (int i = 0; i < 8; i++) {
            sc[i][0] = __expf(sc[i][0] - M0);
            sc[i][1] = __expf(sc[i][1] - M0);
            sc[i][2] = __expf(sc[i][2] - M1);
            sc[i][3] = __expf(sc[i][3] - M1);
            p0 += sc[i][0] + sc[i][1];
            p1 += sc[i][2] + sc[i][3];
        }

        #pragma unroll
        for (int kt = 0; kt < 4; kt++) {
            uint32_t pa[4];
            pa[0] = packh2(sc[2*kt][0],   sc[2*kt][1]);
            pa[1] = packh2(sc[2*kt][2],   sc[2*kt][3]);
            pa[2] = packh2(sc[2*kt+1][0], sc[2*kt+1][1]);
            pa[3] = packh2(sc[2*kt+1][2], sc[2*kt+1][3]);
            const int vrow = kc * 64 + kt * 16 + vrow_c;
            const uint32_t vb_base = sV + vrow * 128;
            const int vsw = vrow & 7;
            #pragma unroll
            for (int dg = 0; dg < 4; dg++) {
                const int ch = dg * 2 + (mi >> 1);
                uint32_t vb[4];
                ldsm4t(vb, vb_base + ((ch ^ vsw) << 4));
                mma16816(of[dg*2],   pa, vb[0], vb[1]);
                mma16816(of[dg*2+1], pa, vb[2], vb[3]);
            }
        }
    }

    p0 += __shfl_xor_sync(0xffffffffu, p0, 1);
    p0 += __shfl_xor_sync(0xffffffffu, p0, 2);
    p1 += __shfl_xor_sync(0xffffffffu, p1, 1);
    p1 += __shfl_xor_sync(0xffffffffu, p1, 2);
    const float i0 = 1.f / p0, i1 = 1.f / p1;

    const size_t o0 = ((size_t)(b * SEQ + n * BLKS + w * 16 + g)) * HID + h * HD;
    const size_t o1 = o0 + (size_t)8 * HID;
    #pragma unroll
    for (int dg = 0; dg < 8; dg++) {
        *(uint32_t*)(g_x16 + o0 + dg * 8 + t2) = packh2(of[dg][0] * i0, of[dg][1] * i0);
        *(uint32_t*)(g_x16 + o1 + dg * 8 + t2) = packh2(of[dg][2] * i1, of[dg][3] * i1);
    }
}

// ---------------------------------------------------------------------------
// Host launcher
// ---------------------------------------------------------------------------
extern "C" void kernel_launch(void* const* d_in, const int* in_sizes, int n_in,
                              void* d_out, int out_size) {
    const float* inputs_q = (const float*)d_in[0];
    const float* wq = (const float*)d_in[1];
    const float* bq = (const float*)d_in[2];
    const float* wk = (const float*)d_in[3];
    const float* bk = (const float*)d_in[4];
    const float* wv = (const float*)d_in[5];
    const float* bv = (const float*)d_in[6];
    const float* w_sort = (const float*)d_in[7];
    const float* b_sort = (const float*)d_in[8];
    const float* wo = (const float*)d_in[9];
    const float* bo = (const float*)d_in[10];
    float* out = (float*)d_out;

    __half *a16, *q16, *k16, *v16, *x16, *wq16, *wk16, *wv16, *wo16;
    cudaGetSymbolAddress((void**)&a16,  g_a16);
    cudaGetSymbolAddress((void**)&q16,  g_q16);
    cudaGetSymbolAddress((void**)&k16,  g_k16);
    cudaGetSymbolAddress((void**)&v16,  g_v16);
    cudaGetSymbolAddress((void**)&x16,  g_x16);
    cudaGetSymbolAddress((void**)&wq16, g_wq16);
    cudaGetSymbolAddress((void**)&wk16, g_wk16);
    cudaGetSymbolAddress((void**)&wv16, g_wv16);
    cudaGetSymbolAddress((void**)&wo16, g_wo16);

    cudaFuncSetAttribute(gemm_hmma, cudaFuncAttributeMaxDynamicSharedMemorySize, GEMM_SMEM);
    cudaFuncSetAttribute(attn_kernel, cudaFuncAttributeMaxDynamicSharedMemorySize, ATT_SMEM);

    const int n4 = ROWS * DM / 4;
    to_half<<<(n4 + 255) / 256, 256>>>(inputs_q, a16, n4);
    transpose_half4<<<dim3(32, 32, 4), dim3(32, 8)>>>(wq, wk, wv, wo,
                                                      wq16, wk16, wv16, wo16);

    dim3 gg(HID / TN, ROWS / TM);
    gemm_hmma<<<gg, 256, GEMM_SMEM>>>(a16, wq16, bq, nullptr, q16);
    gemm_hmma<<<gg, 256, GEMM_SMEM>>>(a16, wk16, bk, nullptr, k16);
    gemm_hmma<<<gg, 256, GEMM_SMEM>>>(a16, wv16, bv, nullptr, v16);

    sumkey_sort<<<BS * NB, 256>>>(w_sort, b_sort);
    sinkhorn_kernel<<<BS, dim3(32, 32)>>>();
    blockmix<<<dim3(PERBLK / 1024, BS, 2), 256>>>();
    attn_kernel<<<dim3(NH, NB, BS), 256, ATT_SMEM>>>();

    gemm_hmma<<<gg, 256, GEMM_SMEM>>>(x16, wo16, bo, out, nullptr);
}

// round 10
// speedup vs baseline: 5.8771x; 1.2696x over previous
#include <cuda_runtime.h>
#include <cuda_fp16.h>
#include <cstdint>

// ---------------------------------------------------------------------------
// SinkhornAttention: BS=4, SEQ=4096, DM=1024, H=16, HD=64, BLK=128, NB=32
// ---------------------------------------------------------------------------
#define BS   4
#define SEQ  4096
#define DM   1024
#define NH   16
#define HD   64
#define BLKS 128
#define NB   32
#define ROWS (BS*SEQ)            // 16384
#define HID  (NH*HD)             // 1024
#define PERB (SEQ*HID)           // 4194304 (elements per batch)
#define PERBLK (BLKS*HID)        // 131072

// GEMM tiling: CTA 128x256, 8 warps (2M x 4N), warp tile 64x64
#define TM 128
#define TN 256
#define KC 32
#define NCHUNK (DM / KC)            // 32
#define ROWB 80                     // 64B data + 16B pad per 32-k row
#define MATB_A (128 * ROWB)         // 10240
#define MATB_B (256 * ROWB)         // 20480
#define STAGE_BYTES (MATB_A + MATB_B)  // 30720
#define NSTAGE 4
#define GEMM_SMEM (NSTAGE * STAGE_BYTES)   // 122880

// Attention smem: Q 16KB @0, K 32KB @16384, V 32KB @49152
#define ATT_SMEM 81920

// ---------------------------------------------------------------------------
// Scratch (device globals: allocation-free per harness rules)
// ---------------------------------------------------------------------------
__device__ float g_sortout[BS*NB*NB];
__device__ float g_perm   [BS*NB*NB];

__device__ __half g_a16[ROWS*DM];    // inputs_q fp16
__device__ __half g_q16[ROWS*HID];
__device__ __half g_k16[ROWS*HID];
__device__ __half g_v16[ROWS*HID];
__device__ __half g_sk16[ROWS*HID];
__device__ __half g_sv16[ROWS*HID];
__device__ __half g_x16[ROWS*HID];
__device__ __half g_wq16[HID*DM];    // transposed [n][k]
__device__ __half g_wk16[HID*DM];
__device__ __half g_wv16[HID*DM];
__device__ __half g_wo16[DM*HID];

// ---------------------------------------------------------------------------
// PTX helpers
// ---------------------------------------------------------------------------
__device__ __forceinline__ void cp16(uint32_t s, const void* g) {
    asm volatile("cp.async.cg.shared.global [%0], [%1], 16;" :: "r"(s), "l"(g));
}
#define CP_COMMIT() asm volatile("cp.async.commit_group;" ::: "memory")
#define CP_WAIT(n)  asm volatile("cp.async.wait_group %0;" :: "n"(n) : "memory")

__device__ __forceinline__ void ldsm4(uint32_t* r, uint32_t addr) {
    asm volatile("ldmatrix.sync.aligned.m8n8.x4.shared.b16 {%0,%1,%2,%3}, [%4];"
                 : "=r"(r[0]), "=r"(r[1]), "=r"(r[2]), "=r"(r[3]) : "r"(addr));
}
__device__ __forceinline__ void ldsm4t(uint32_t* r, uint32_t addr) {
    asm volatile("ldmatrix.sync.aligned.m8n8.x4.trans.shared.b16 {%0,%1,%2,%3}, [%4];"
                 : "=r"(r[0]), "=r"(r[1]), "=r"(r[2]), "=r"(r[3]) : "r"(addr));
}
__device__ __forceinline__ void mma16816(float* c, const uint32_t* a,
                                         uint32_t b0, uint32_t b1) {
    asm volatile("mma.sync.aligned.m16n8k16.row.col.f32.f16.f16.f32 "
                 "{%0,%1,%2,%3}, {%4,%5,%6,%7}, {%8,%9}, {%0,%1,%2,%3};"
                 : "+f"(c[0]), "+f"(c[1]), "+f"(c[2]), "+f"(c[3])
                 : "r"(a[0]), "r"(a[1]), "r"(a[2]), "r"(a[3]), "r"(b0), "r"(b1));
}
__device__ __forceinline__ uint32_t packh2(float a, float b) {
    __half2 h = __floats2half2_rn(a, b);
    return *(uint32_t*)&h;
}

// ---------------------------------------------------------------------------
// Convert fp32 -> fp16
// ---------------------------------------------------------------------------
__global__ __launch_bounds__(256)
void to_half(const float* __restrict__ src, __half* __restrict__ dst, int n4) {
    int i = blockIdx.x * 256 + threadIdx.x;
    if (i >= n4) return;
    float4 f = ((const float4*)src)[i];
    __half2 h0, h1;
    h0.x = __float2half_rn(f.x); h0.y = __float2half_rn(f.y);
    h1.x = __float2half_rn(f.z); h1.y = __float2half_rn(f.w);
    ((__half2*)dst)[i*2]   = h0;
    ((__half2*)dst)[i*2+1] = h1;
}

// ---------------------------------------------------------------------------
// Transpose 4x 1024x1024 fp32 W[k][n] -> fp16 Wt[n][k], fused (grid.z selects)
// ---------------------------------------------------------------------------
__global__ __launch_bounds__(256)
void transpose_half4(const float* __restrict__ W0, const float* __restrict__ W1,
                     const float* __restrict__ W2, const float* __restrict__ W3,
                     __half* __restrict__ T0, __half* __restrict__ T1,
                     __half* __restrict__ T2, __half* __restrict__ T3) {
    const float* W = (blockIdx.z == 0) ? W0 : (blockIdx.z == 1) ? W1
                   : (blockIdx.z == 2) ? W2 : W3;
    __half* T = (blockIdx.z == 0) ? T0 : (blockIdx.z == 1) ? T1
              : (blockIdx.z == 2) ? T2 : T3;
    __shared__ float t[32][33];
    const int tx = threadIdx.x, ty = threadIdx.y;
    const int x = blockIdx.x * 32 + tx;
    const int y0 = blockIdx.y * 32;
    #pragma unroll
    for (int i = ty; i < 32; i += 8) t[i][tx] = W[(size_t)(y0 + i) * 1024 + x];
    __syncthreads();
    const int k = y0 + tx;
    #pragma unroll
    for (int i = ty; i < 32; i += 8) {
        int n = blockIdx.x * 32 + i;
        T[(size_t)n * 1024 + k] = __float2half_rn(t[tx][i]);
    }
}

// ---------------------------------------------------------------------------
// HMMA GEMM, software-pipelined fragments, grid.z selects (B, bias, out).
// C = A * B^T + bias; fp32 out (Cf) when non-null else fp16 (Ch).
// ---------------------------------------------------------------------------
__global__ __launch_bounds__(256, 1)
void gemm_hmma(const __half* __restrict__ A,
               const __half* __restrict__ B0, const __half* __restrict__ B1,
               const __half* __restrict__ B2,
               const float* __restrict__ bi0, const float* __restrict__ bi1,
               const float* __restrict__ bi2,
               float* __restrict__ Cf,
               __half* __restrict__ Ch0, __half* __restrict__ Ch1,
               __half* __restrict__ Ch2) {
    const int z = blockIdx.z;
    const __half* __restrict__ B  = (z == 0) ? B0 : (z == 1) ? B1 : B2;
    const float* __restrict__ bias = (z == 0) ? bi0 : (z == 1) ? bi1 : bi2;
    __half* __restrict__ Ch = (z == 0) ? Ch0 : (z == 1) ? Ch1 : Ch2;

    extern __shared__ __align__(128) char smem[];
    const uint32_t sbase = (uint32_t)__cvta_generic_to_shared(smem);

    const int tid  = threadIdx.x;
    const int wid  = tid >> 5, lane = tid & 31;
    const int wm   = wid >> 2;
    const int wn   = wid & 3;
    const int bx0  = blockIdx.x * TN;
    const int by0  = blockIdx.y * TM;

    const int rr  = tid >> 2;
    const int c16 = tid & 3;

    auto load_stage = [&](int c, int s) {
        const uint32_t st = sbase + (uint32_t)s * STAGE_BYTES;
        const size_t kof = (size_t)c * KC + c16 * 8;
        #pragma unroll
        for (int i = 0; i < 2; i++) {
            const int row = rr + i * 64;
            cp16(st + (uint32_t)(row * ROWB + c16 * 16),
                 A + (size_t)(by0 + row) * DM + kof);
        }
        #pragma unroll
        for (int i = 0; i < 4; i++) {
            const int row = rr + i * 64;
            cp16(st + MATB_A + (uint32_t)(row * ROWB + c16 * 16),
                 B + (size_t)(bx0 + row) * DM + kof);
        }
    };

    const int mi   = lane >> 3;
    const int lrow = lane & 7;
    const uint32_t aoff = (uint32_t)(((mi & 1) * 8 + lrow) * ROWB + (mi >> 1) * 16);
    const uint32_t boff = (uint32_t)(((mi >> 1) * 8 + lrow) * ROWB + (mi & 1) * 16);

    float acc[4][8][4];
    #pragma unroll
    for (int i = 0; i < 4; i++)
        #pragma unroll
        for (int j = 0; j < 8; j++)
            #pragma unroll
            for (int k = 0; k < 4; k++) acc[i][j][k] = 0.f;

    load_stage(0, 0); CP_COMMIT();
    load_stage(1, 1); CP_COMMIT();
    load_stage(2, 2); CP_COMMIT();

    for (int c = 0; c < NCHUNK; c++) {
        CP_WAIT(2);
        __syncthreads();

        const uint32_t st = sbase + (uint32_t)(c & 3) * STAGE_BYTES;
        const uint32_t sA = st, sB = st + MATB_A;

        // -- load ALL fragments for both k16-steps up front (ILP over LDSM)
        uint32_t a0[4][4], b0[4][4], a1[4][4], b1[4][4];
        #pragma unroll
        for (int mt = 0; mt < 4; mt++) {
            const uint32_t ro = (uint32_t)((wm * 64 + mt * 16) * ROWB) + aoff;
            ldsm4(a0[mt], sA + ro);
            ldsm4(a1[mt], sA + ro + 32);
        }
        #pragma unroll
        for (int nb = 0; nb < 4; nb++) {
            const uint32_t ro = (uint32_t)((wn * 64 + nb * 16) * ROWB) + boff;
            ldsm4(b0[nb], sB + ro);
            ldsm4(b1[nb], sB + ro + 32);
        }

        // -- MMAs for ks=0 (LDSM of ks=1 retires underneath)
        #pragma unroll
        for (int mt = 0; mt < 4; mt++)
            #pragma unroll
            for (int nt = 0; nt < 8; nt++) {
                const int p = nt >> 1, q = (nt & 1) * 2;
                mma16816(acc[mt][nt], a0[mt], b0[p][q], b0[p][q+1]);
            }

        // -- issue next stage's cp.async under the remaining MMAs
        if (c + 3 < NCHUNK) load_stage(c + 3, (c + 3) & 3);
        CP_COMMIT();

        // -- MMAs for ks=1
        #pragma unroll
        for (int mt = 0; mt < 4; mt++)
            #pragma unroll
            for (int nt = 0; nt < 8; nt++) {
                const int p = nt >> 1, q = (nt & 1) * 2;
                mma16816(acc[mt][nt], a1[mt], b1[p][q], b1[p][q+1]);
            }
    }

    const int g = lane >> 2, t2 = (lane & 3) * 2;
    #pragma unroll
    for (int mt = 0; mt < 4; mt++) {
        const int row0 = by0 + wm * 64 + mt * 16 + g;
        #pragma unroll
        for (int nt = 0; nt < 8; nt++) {
            const int col = bx0 + wn * 64 + nt * 8 + t2;
            const float2 bv = *(const float2*)(bias + col);
            float o00 = acc[mt][nt][0] + bv.x, o01 = acc[mt][nt][1] + bv.y;
            float o10 = acc[mt][nt][2] + bv.x, o11 = acc[mt][nt][3] + bv.y;
            if (Cf) {
                *(float2*)(Cf + (size_t)row0 * HID + col)       = make_float2(o00, o01);
                *(float2*)(Cf + (size_t)(row0 + 8) * HID + col) = make_float2(o10, o11);
            } else {
                *(uint32_t*)(Ch + (size_t)row0 * HID + col)       = packh2(o00, o01);
                *(uint32_t*)(Ch + (size_t)(row0 + 8) * HID + col) = packh2(o10, o11);
            }
        }
    }
}

// ---------------------------------------------------------------------------
// sum_key + sort logits (reads fp16 K)
// ---------------------------------------------------------------------------
__global__ __launch_bounds__(256)
void sumkey_sort(const float* __restrict__ w_sort, const float* __restrict__ b_sort) {
    __shared__ float sk[HID];
    const int bn = blockIdx.x;
    const int b = bn >> 5, n = bn & 31;
    const int t = threadIdx.x;

    const __half* base = g_k16 + ((size_t)(b * SEQ + n * BLKS)) * HID;
    for (int c = t; c < HID; c += 256) {
        float s = 0.f;
        for (int r = 0; r < BLKS; r++) s += __half2float(base[(size_t)r * HID + c]);
        sk[c] = s;
    }
    __syncthreads();

    const int warp = t >> 5, lane = t & 31;
    for (int m = warp; m < NB; m += 8) {
        float s = 0.f;
        for (int c = lane; c < HID; c += 32) s += sk[c] * w_sort[c * NB + m];
        #pragma unroll
        for (int o = 16; o; o >>= 1) s += __shfl_xor_sync(0xffffffffu, s, o);
        if (lane == 0) g_sortout[b * (NB*NB) + n * NB + m] = s + b_sort[m];
    }
}

// ---------------------------------------------------------------------------
// Sinkhorn
// ---------------------------------------------------------------------------
__global__ void sinkhorn_kernel() {
    __shared__ float la[32][33];
    __shared__ float colLse[32];
    const int b = blockIdx.x;
    const int j = threadIdx.x, i = threadIdx.y;

    float v = g_sortout[b * (NB*NB) + i * NB + j];

    for (int it = 0; it < 5; it++) {
        float mx = v;
        #pragma unroll
        for (int o = 16; o; o >>= 1) mx = fmaxf(mx, __shfl_xor_sync(0xffffffffu, mx, o));
        float sum = expf(v - mx);
        #pragma unroll
        for (int o = 16; o; o >>= 1) sum += __shfl_xor_sync(0xffffffffu, sum, o);
        v -= mx + logf(sum);

        la[i][j] = v;
        __syncthreads();

        float cv = la[j][i];
        float cm = cv;
        #pragma unroll
        for (int o = 16; o; o >>= 1) cm = fmaxf(cm, __shfl_xor_sync(0xffffffffu, cm, o));
        float cs = expf(cv - cm);
        #pragma unroll
        for (int o = 16; o; o >>= 1) cs += __shfl_xor_sync(0xffffffffu, cs, o);
        if (j == 0) colLse[i] = cm + logf(cs);
        __syncthreads();

        v -= colLse[j];
        __syncthreads();
    }
    g_perm[b * (NB*NB) + i * NB + j] = expf(fminf(fmaxf(v, -1.f), 1.f));
}

// ---------------------------------------------------------------------------
// blockmix (fp16 in/out, fp32 accumulate)
// ---------------------------------------------------------------------------
__global__ __launch_bounds__(256)
void blockmix() {
    __shared__ float p[NB][NB];
    const int b = blockIdx.y;
    const int which = blockIdx.z;
    const __half2* __restrict__ src = (const __half2*)(which ? g_v16 : g_k16);
    __half2* __restrict__ dst = (__half2*)(which ? g_sv16 : g_sk16);

    const int t = threadIdx.x;
    for (int i = t; i < NB * NB; i += 256) p[i / NB][i % NB] = g_perm[b * (NB*NB) + i];
    __syncthreads();

    const size_t base = (size_t)b * (PERB/2) + (size_t)blockIdx.x * 512;

    float2 acc[NB][2];
    #pragma unroll
    for (int i = 0; i < NB; i++) { acc[i][0] = make_float2(0.f,0.f); acc[i][1] = make_float2(0.f,0.f); }

    for (int m = 0; m < NB; m++) {
        float2 f0 = __half22float2(src[base + (size_t)m * (PERBLK/2) + t]);
        float2 f1 = __half22float2(src[base + (size_t)m * (PERBLK/2) + t + 256]);
        #pragma unroll
        for (int n = 0; n < NB; n++) {
            float pm = p[n][m];
            acc[n][0].x += pm * f0.x; acc[n][0].y += pm * f0.y;
            acc[n][1].x += pm * f1.x; acc[n][1].y += pm * f1.y;
        }
    }

    #pragma unroll
    for (int n = 0; n < NB; n++) {
        dst[base + (size_t)n * (PERBLK/2) + t]       = __floats2half2_rn(acc[n][0].x, acc[n][0].y);
        dst[base + (size_t)n * (PERBLK/2) + t + 256] = __floats2half2_rn(acc[n][1].x, acc[n][1].y);
    }
}

// ---------------------------------------------------------------------------
// Block attention, fp16 HMMA (unchanged)
// ---------------------------------------------------------------------------
__global__ __launch_bounds__(256, 2)
void attn_kernel() {
    extern __shared__ __align__(128) char sm[];
    const uint32_t sb = (uint32_t)__cvta_generic_to_shared(sm);
    const uint32_t sQ = sb, sK = sb + 16384, sV = sb + 49152;

    const int h = blockIdx.x, n = blockIdx.y, b = blockIdx.z;
    const int t = threadIdx.x;
    const int w = t >> 5, lane = t & 31;

    const __half* qg = g_q16 + ((size_t)(b * SEQ + n * BLKS)) * HID + h * HD;
    #pragma unroll
    for (int i = 0; i < 4; i++) {
        const int task = t + i * 256;
        const int row = task >> 3, ch = task & 7;
        cp16(sQ + row * 128 + (((ch ^ row) & 7) << 4), qg + (size_t)row * HID + ch * 8);
    }
    #pragma unroll
    for (int i = 0; i < 8; i++) {
        const int task = t + i * 256;
        const int row = task >> 3, ch = task & 7;
        const __half* kp = (row < BLKS)
            ? g_k16 + ((size_t)(b * SEQ + n * BLKS + row)) * HID + h * HD
            : g_sk16 + (size_t)b * PERB + (size_t)n * PERBLK + (size_t)(row - BLKS) * HID + h * HD;
        cp16(sK + row * 128 + (((ch ^ row) & 7) << 4), kp + ch * 8);
    }
    #pragma unroll
    for (int i = 0; i < 8; i++) {
        const int task = t + i * 256;
        const int row = task >> 3, ch = task & 7;
        const __half* vp = (row < BLKS)
            ? g_v16 + ((size_t)(b * SEQ + n * BLKS + row)) * HID + h * HD
            : g_sv16 + (size_t)b * PERB + (size_t)n * PERBLK + (size_t)(row - BLKS) * HID + h * HD;
        cp16(sV + row * 128 + (((ch ^ row) & 7) << 4), vp + ch * 8);
    }
    CP_COMMIT(); CP_WAIT(0);
    __syncthreads();

    const int mi = lane >> 3, lrow = lane & 7;
    const int g = lane >> 2, t2 = (lane & 3) * 2;

    uint32_t qa[4][4];
    {
        const int qrow = w * 16 + (mi & 1) * 8 + lrow;
        const uint32_t qb = sQ + qrow * 128;
        const int qsw = qrow & 7;
        #pragma unroll
        for (int kt = 0; kt < 4; kt++) {
            const int ch = kt * 2 + (mi >> 1);
            ldsm4(qa[kt], qb + ((ch ^ qsw) << 4));
        }
    }

    float of[8][4];
    #pragma unroll
    for (int i = 0; i < 8; i++)
        #pragma unroll
        for (int j = 0; j < 4; j++) of[i][j] = 0.f;
    float M0 = -1e30f, M1 = -1e30f, p0 = 0.f, p1 = 0.f;

    const int krow_c = (mi >> 1) * 8 + lrow;
    const int vrow_c = (mi & 1) * 8 + lrow;

    for (int kc = 0; kc < 4; kc++) {
        float sc[8][4];
        #pragma unroll
        for (int i = 0; i < 8; i++)
            #pragma unroll
            for (int j = 0; j < 4; j++) sc[i][j] = 0.f;

        #pragma unroll
        for (int kt = 0; kt < 4; kt++) {
            #pragma unroll
            for (int ng = 0; ng < 4; ng++) {
                const int krow = kc * 64 + ng * 16 + krow_c;
                const int ch = kt * 2 + (mi & 1);
                uint32_t kb[4];
                ldsm4(kb, sK + krow * 128 + (((ch ^ krow) & 7) << 4));
                mma16816(sc[ng*2],   qa[kt], kb[0], kb[1]);
                mma16816(sc[ng*2+1], qa[kt], kb[2], kb[3]);
            }
        }
        #pragma unroll
        for (int i = 0; i < 8; i++)
            #pragma unroll
            for (int j = 0; j < 4; j++) sc[i][j] *= 0.125f;

        float m0 = -1e30f, m1 = -1e30f;
        #pragma unroll
        for (int i = 0; i < 8; i++) {
            m0 = fmaxf(m0, fmaxf(sc[i][0], sc[i][1]));
            m1 = fmaxf(m1, fmaxf(sc[i][2], sc[i][3]));
        }
        m0 = fmaxf(m0, __shfl_xor_sync(0xffffffffu, m0, 1));
        m0 = fmaxf(m0, __shfl_xor_sync(0xffffffffu, m0, 2));
        m1 = fmaxf(m1, __shfl_xor_sync(0xffffffffu, m1, 1));
        m1 = fmaxf(m1, __shfl_xor_sync(0xffffffffu, m1, 2));

        const float nM0 = fmaxf(M0, m0), nM1 = fmaxf(M1, m1);
        const float c0 = __expf(M0 - nM0), c1 = __expf(M1 - nM1);
        p0 *= c0; p1 *= c1;
        #pragma unroll
        for (int i = 0; i < 8; i++) {
            of[i][0] *= c0; of[i][1] *= c0;
            of[i][2] *= c1; of[i][3] *= c1;
        }
        M0 = nM0; M1 = nM1;

        #pragma unroll
        for (int i = 0; i < 8; i++) {
            sc[i][0] = __expf(sc[i][0] - M0);
            sc[i][1] = __expf(sc[i][1] - M0);
            sc[i][2] = __expf(sc[i][2] - M1);
            sc[i][3] = __expf(sc[i][3] - M1);
            p0 += sc[i][0] + sc[i][1];
            p1 += sc[i][2] + sc[i][3];
        }

        #pragma unroll
        for (int kt = 0; kt < 4; kt++) {
            uint32_t pa[4];
            pa[0] = packh2(sc[2*kt][0],   sc[2*kt][1]);
            pa[1] = packh2(sc[2*kt][2],   sc[2*kt][3]);
            pa[2] = packh2(sc[2*kt+1][0], sc[2*kt+1][1]);
            pa[3] = packh2(sc[2*kt+1][2], sc[2*kt+1][3]);
            const int vrow = kc * 64 + kt * 16 + vrow_c;
            const uint32_t vb_base = sV + vrow * 128;
            const int vsw = vrow & 7;
            #pragma unroll
            for (int dg = 0; dg < 4; dg++) {
                const int ch = dg * 2 + (mi >> 1);
                uint32_t vb[4];
                ldsm4t(vb, vb_base + ((ch ^ vsw) << 4));
                mma16816(of[dg*2],   pa, vb[0], vb[1]);
                mma16816(of[dg*2+1], pa, vb[2], vb[3]);
            }
        }
    }

    p0 += __shfl_xor_sync(0xffffffffu, p0, 1);
    p0 += __shfl_xor_sync(0xffffffffu, p0, 2);
    p1 += __shfl_xor_sync(0xffffffffu, p1, 1);
    p1 += __shfl_xor_sync(0xffffffffu, p1, 2);
    const float i0 = 1.f / p0, i1 = 1.f / p1;

    const size_t o0 = ((size_t)(b * SEQ + n * BLKS + w * 16 + g)) * HID + h * HD;
    const size_t o1 = o0 + (size_t)8 * HID;
    #pragma unroll
    for (int dg = 0; dg < 8; dg++) {
        *(uint32_t*)(g_x16 + o0 + dg * 8 + t2) = packh2(of[dg][0] * i0, of[dg][1] * i0);
        *(uint32_t*)(g_x16 + o1 + dg * 8 + t2) = packh2(of[dg][2] * i1, of[dg][3] * i1);
    }
}

// ---------------------------------------------------------------------------
// Host launcher
// ---------------------------------------------------------------------------
extern "C" void kernel_launch(void* const* d_in, const int* in_sizes, int n_in,
                              void* d_out, int out_size) {
    const float* inputs_q = (const float*)d_in[0];
    const float* wq = (const float*)d_in[1];
    const float* bq = (const float*)d_in[2];
    const float* wk = (const float*)d_in[3];
    const float* bk = (const float*)d_in[4];
    const float* wv = (const float*)d_in[5];
    const float* bv = (const float*)d_in[6];
    const float* w_sort = (const float*)d_in[7];
    const float* b_sort = (const float*)d_in[8];
    const float* wo = (const float*)d_in[9];
    const float* bo = (const float*)d_in[10];
    float* out = (float*)d_out;

    __half *a16, *q16, *k16, *v16, *x16, *wq16, *wk16, *wv16, *wo16;
    cudaGetSymbolAddress((void**)&a16,  g_a16);
    cudaGetSymbolAddress((void**)&q16,  g_q16);
    cudaGetSymbolAddress((void**)&k16,  g_k16);
    cudaGetSymbolAddress((void**)&v16,  g_v16);
    cudaGetSymbolAddress((void**)&x16,  g_x16);
    cudaGetSymbolAddress((void**)&wq16, g_wq16);
    cudaGetSymbolAddress((void**)&wk16, g_wk16);
    cudaGetSymbolAddress((void**)&wv16, g_wv16);
    cudaGetSymbolAddress((void**)&wo16, g_wo16);

    cudaFuncSetAttribute(gemm_hmma, cudaFuncAttributeMaxDynamicSharedMemorySize, GEMM_SMEM);
    cudaFuncSetAttribute(attn_kernel, cudaFuncAttributeMaxDynamicSharedMemorySize, ATT_SMEM);

    const int n4 = ROWS * DM / 4;
    to_half<<<(n4 + 255) / 256, 256>>>(inputs_q, a16, n4);
    transpose_half4<<<dim3(32, 32, 4), dim3(32, 8)>>>(wq, wk, wv, wo,
                                                      wq16, wk16, wv16, wo16);

    // Fused Q/K/V projection: grid.z selects weight/bias/output
    gemm_hmma<<<dim3(HID / TN, ROWS / TM, 3), 256, GEMM_SMEM>>>(
        a16, wq16, wk16, wv16, bq, bk, bv, nullptr, q16, k16, v16);

    sumkey_sort<<<BS * NB, 256>>>(w_sort, b_sort);
    sinkhorn_kernel<<<BS, dim3(32, 32)>>>();
    blockmix<<<dim3(PERBLK / 1024, BS, 2), 256>>>();
    attn_kernel<<<dim3(NH, NB, BS), 256, ATT_SMEM>>>();

    // Output projection (fp32 out)
    gemm_hmma<<<dim3(HID / TN, ROWS / TM, 1), 256, GEMM_SMEM>>>(
        x16, wo16, wo16, wo16, bo, bo, bo, out, nullptr, nullptr, nullptr);
}

// round 13
// speedup vs baseline: 7.0016x; 1.1914x over previous
#include <cuda_runtime.h>
#include <cuda_fp16.h>
#include <cstdint>

// ---------------------------------------------------------------------------
// SinkhornAttention: BS=4, SEQ=4096, DM=1024, H=16, HD=64, BLK=128, NB=32
// ---------------------------------------------------------------------------
#define BS   4
#define SEQ  4096
#define DM   1024
#define NH   16
#define HD   64
#define BLKS 128
#define NB   32
#define ROWS (BS*SEQ)            // 16384
#define HID  (NH*HD)             // 1024
#define PERB (SEQ*HID)           // 4194304 (elements per batch)
#define PERBLK (BLKS*HID)        // 131072

// GEMM tiling: CTA 128x256, 8 warps (2M x 4N), warp tile 64x64 (R10-proven)
#define TM 128
#define TN 256
#define KC 32
#define NCHUNK (DM / KC)            // 32
#define ROWB 80                     // 64B data + 16B pad per 32-k row
#define MATB_A (128 * ROWB)         // 10240
#define MATB_B (256 * ROWB)         // 20480
#define STAGE_BYTES (MATB_A + MATB_B)  // 30720
#define NSTAGE 4
#define GEMM_SMEM (NSTAGE * STAGE_BYTES)   // 122880

// Attention smem: Q 16KB @0, K 32KB @16384, V 32KB @49152
#define ATT_SMEM 81920

// blockmix smem: K rows 32 x (2048B + 16 pad) + perm 32*80
#define BM_KSTRIDE 2064
#define BM_PERM_OFF (32 * BM_KSTRIDE)        // 66048
#define BM_SMEM (BM_PERM_OFF + 32 * 80)      // 68608

// ---------------------------------------------------------------------------
// Scratch (device globals: allocation-free per harness rules)
// ---------------------------------------------------------------------------
__device__ float g_sortout[BS*NB*NB];
__device__ float g_perm   [BS*NB*NB];

__device__ __half g_a16[ROWS*DM];    // inputs_q fp16
__device__ __half g_q16[ROWS*HID];
__device__ __half g_k16[ROWS*HID];
__device__ __half g_v16[ROWS*HID];
__device__ __half g_sk16[ROWS*HID];
__device__ __half g_sv16[ROWS*HID];
__device__ __half g_x16[ROWS*HID];
__device__ __half g_wq16[HID*DM];    // transposed [n][k]
__device__ __half g_wk16[HID*DM];
__device__ __half g_wv16[HID*DM];
__device__ __half g_wo16[DM*HID];

// ---------------------------------------------------------------------------
// PTX helpers
// ---------------------------------------------------------------------------
__device__ __forceinline__ void cp16(uint32_t s, const void* g) {
    asm volatile("cp.async.cg.shared.global [%0], [%1], 16;" :: "r"(s), "l"(g));
}
#define CP_COMMIT() asm volatile("cp.async.commit_group;" ::: "memory")
#define CP_WAIT(n)  asm volatile("cp.async.wait_group %0;" :: "n"(n) : "memory")

__device__ __forceinline__ void ldsm4(uint32_t* r, uint32_t addr) {
    asm volatile("ldmatrix.sync.aligned.m8n8.x4.shared.b16 {%0,%1,%2,%3}, [%4];"
                 : "=r"(r[0]), "=r"(r[1]), "=r"(r[2]), "=r"(r[3]) : "r"(addr));
}
__device__ __forceinline__ void ldsm4t(uint32_t* r, uint32_t addr) {
    asm volatile("ldmatrix.sync.aligned.m8n8.x4.trans.shared.b16 {%0,%1,%2,%3}, [%4];"
                 : "=r"(r[0]), "=r"(r[1]), "=r"(r[2]), "=r"(r[3]) : "r"(addr));
}
__device__ __forceinline__ void mma16816(float* c, const uint32_t* a,
                                         uint32_t b0, uint32_t b1) {
    asm volatile("mma.sync.aligned.m16n8k16.row.col.f32.f16.f16.f32 "
                 "{%0,%1,%2,%3}, {%4,%5,%6,%7}, {%8,%9}, {%0,%1,%2,%3};"
                 : "+f"(c[0]), "+f"(c[1]), "+f"(c[2]), "+f"(c[3])
                 : "r"(a[0]), "r"(a[1]), "r"(a[2]), "r"(a[3]), "r"(b0), "r"(b1));
}
__device__ __forceinline__ uint32_t packh2(float a, float b) {
    __half2 h = __floats2half2_rn(a, b);
    return *(uint32_t*)&h;
}

// ---------------------------------------------------------------------------
// Convert fp32 -> fp16
// ---------------------------------------------------------------------------
__global__ __launch_bounds__(256)
void to_half(const float* __restrict__ src, __half* __restrict__ dst, int n4) {
    int i = blockIdx.x * 256 + threadIdx.x;
    if (i >= n4) return;
    float4 f = ((const float4*)src)[i];
    __half2 h0, h1;
    h0.x = __float2half_rn(f.x); h0.y = __float2half_rn(f.y);
    h1.x = __float2half_rn(f.z); h1.y = __float2half_rn(f.w);
    ((__half2*)dst)[i*2]   = h0;
    ((__half2*)dst)[i*2+1] = h1;
}

// ---------------------------------------------------------------------------
// Transpose 4x 1024x1024 fp32 W[k][n] -> fp16 Wt[n][k], fused (grid.z selects)
// ---------------------------------------------------------------------------
__global__ __launch_bounds__(256)
void transpose_half4(const float* __restrict__ W0, const float* __restrict__ W1,
                     const float* __restrict__ W2, const float* __restrict__ W3,
                     __half* __restrict__ T0, __half* __restrict__ T1,
                     __half* __restrict__ T2, __half* __restrict__ T3) {
    const float* W = (blockIdx.z == 0) ? W0 : (blockIdx.z == 1) ? W1
                   : (blockIdx.z == 2) ? W2 : W3;
    __half* T = (blockIdx.z == 0) ? T0 : (blockIdx.z == 1) ? T1
              : (blockIdx.z == 2) ? T2 : T3;
    __shared__ float t[32][33];
    const int tx = threadIdx.x, ty = threadIdx.y;
    const int x = blockIdx.x * 32 + tx;
    const int y0 = blockIdx.y * 32;
    #pragma unroll
    for (int i = ty; i < 32; i += 8) t[i][tx] = W[(size_t)(y0 + i) * 1024 + x];
    __syncthreads();
    const int k = y0 + tx;
    #pragma unroll
    for (int i = ty; i < 32; i += 8) {
        int n = blockIdx.x * 32 + i;
        T[(size_t)n * 1024 + k] = __float2half_rn(t[tx][i]);
    }
}

// ---------------------------------------------------------------------------
// HMMA GEMM (R10-proven body): KC=32, 4-stage cp.async, fragment SW pipeline.
// grid.z selects (B, bias, out). fp32 out (Cf) when non-null else fp16 (Ch).
// ---------------------------------------------------------------------------
__global__ __launch_bounds__(256, 1)
void gemm_hmma(const __half* __restrict__ A,
               const __half* __restrict__ B0, const __half* __restrict__ B1,
               const __half* __restrict__ B2,
               const float* __restrict__ bi0, const float* __restrict__ bi1,
               const float* __restrict__ bi2,
               float* __restrict__ Cf,
               __half* __restrict__ Ch0, __half* __restrict__ Ch1,
               __half* __restrict__ Ch2) {
    const int z = blockIdx.z;
    const __half* __restrict__ B  = (z == 0) ? B0 : (z == 1) ? B1 : B2;
    const float* __restrict__ bias = (z == 0) ? bi0 : (z == 1) ? bi1 : bi2;
    __half* __restrict__ Ch = (z == 0) ? Ch0 : (z == 1) ? Ch1 : Ch2;

    extern __shared__ __align__(128) char smem[];
    const uint32_t sbase = (uint32_t)__cvta_generic_to_shared(smem);

    const int tid  = threadIdx.x;
    const int wid  = tid >> 5, lane = tid & 31;
    const int wm   = wid >> 2;
    const int wn   = wid & 3;
    const int bx0  = blockIdx.x * TN;
    const int by0  = blockIdx.y * TM;

    const int rr  = tid >> 2;
    const int c16 = tid & 3;

    auto load_stage = [&](int c, int s) {
        const uint32_t st = sbase + (uint32_t)s * STAGE_BYTES;
        const size_t kof = (size_t)c * KC + c16 * 8;
        #pragma unroll
        for (int i = 0; i < 2; i++) {
            const int row = rr + i * 64;
            cp16(st + (uint32_t)(row * ROWB + c16 * 16),
                 A + (size_t)(by0 + row) * DM + kof);
        }
        #pragma unroll
        for (int i = 0; i < 4; i++) {
            const int row = rr + i * 64;
            cp16(st + MATB_A + (uint32_t)(row * ROWB + c16 * 16),
                 B + (size_t)(bx0 + row) * DM + kof);
        }
    };

    const int mi   = lane >> 3;
    const int lrow = lane & 7;
    const uint32_t aoff = (uint32_t)(((mi & 1) * 8 + lrow) * ROWB + (mi >> 1) * 16);
    const uint32_t boff = (uint32_t)(((mi >> 1) * 8 + lrow) * ROWB + (mi & 1) * 16);

    float acc[4][8][4];
    #pragma unroll
    for (int i = 0; i < 4; i++)
        #pragma unroll
        for (int j = 0; j < 8; j++)
            #pragma unroll
            for (int k = 0; k < 4; k++) acc[i][j][k] = 0.f;

    load_stage(0, 0); CP_COMMIT();
    load_stage(1, 1); CP_COMMIT();
    load_stage(2, 2); CP_COMMIT();

    for (int c = 0; c < NCHUNK; c++) {
        CP_WAIT(2);
        __syncthreads();

        const uint32_t st = sbase + (uint32_t)(c & 3) * STAGE_BYTES;
        const uint32_t sA = st, sB = st + MATB_A;

        uint32_t a0[4][4], b0[4][4], a1[4][4], b1[4][4];
        #pragma unroll
        for (int mt = 0; mt < 4; mt++) {
            const uint32_t ro = (uint32_t)((wm * 64 + mt * 16) * ROWB) + aoff;
            ldsm4(a0[mt], sA + ro);
            ldsm4(a1[mt], sA + ro + 32);
        }
        #pragma unroll
        for (int nb = 0; nb < 4; nb++) {
            const uint32_t ro = (uint32_t)((wn * 64 + nb * 16) * ROWB) + boff;
            ldsm4(b0[nb], sB + ro);
            ldsm4(b1[nb], sB + ro + 32);
        }

        #pragma unroll
        for (int mt = 0; mt < 4; mt++)
            #pragma unroll
            for (int nt = 0; nt < 8; nt++) {
                const int p = nt >> 1, q = (nt & 1) * 2;
                mma16816(acc[mt][nt], a0[mt], b0[p][q], b0[p][q+1]);
            }

        if (c + 3 < NCHUNK) load_stage(c + 3, (c + 3) & 3);
        CP_COMMIT();

        #pragma unroll
        for (int mt = 0; mt < 4; mt++)
            #pragma unroll
            for (int nt = 0; nt < 8; nt++) {
                const int p = nt >> 1, q = (nt & 1) * 2;
                mma16816(acc[mt][nt], a1[mt], b1[p][q], b1[p][q+1]);
            }
    }

    const int g = lane >> 2, t2 = (lane & 3) * 2;
    #pragma unroll
    for (int mt = 0; mt < 4; mt++) {
        const int row0 = by0 + wm * 64 + mt * 16 + g;
        #pragma unroll
        for (int nt = 0; nt < 8; nt++) {
            const int col = bx0 + wn * 64 + nt * 8 + t2;
            const float2 bv = *(const float2*)(bias + col);
            float o00 = acc[mt][nt][0] + bv.x, o01 = acc[mt][nt][1] + bv.y;
            float o10 = acc[mt][nt][2] + bv.x, o11 = acc[mt][nt][3] + bv.y;
            if (Cf) {
                *(float2*)(Cf + (size_t)row0 * HID + col)       = make_float2(o00, o01);
                *(float2*)(Cf + (size_t)(row0 + 8) * HID + col) = make_float2(o10, o11);
            } else {
                *(uint32_t*)(Ch + (size_t)row0 * HID + col)       = packh2(o00, o01);
                *(uint32_t*)(Ch + (size_t)(row0 + 8) * HID + col) = packh2(o10, o11);
            }
        }
    }
}

// ---------------------------------------------------------------------------
// sum_key + sort logits: 512 threads, half2 columns, MLP-unrolled row loop
// ---------------------------------------------------------------------------
__global__ __launch_bounds__(512)
void sumkey_sort(const float* __restrict__ w_sort, const float* __restrict__ b_sort) {
    __shared__ float sk[HID];
    const int bn = blockIdx.x;
    const int b = bn >> 5, n = bn & 31;
    const int t = threadIdx.x;        // 0..511 = half2 column

    const __half2* base = (const __half2*)(g_k16 + ((size_t)(b * SEQ + n * BLKS)) * HID);
    float2 s0 = {0.f,0.f}, s1 = {0.f,0.f}, s2 = {0.f,0.f}, s3 = {0.f,0.f};
    #pragma unroll 8
    for (int r = 0; r < BLKS; r += 4) {
        float2 f0 = __half22float2(base[(size_t)(r+0) * 512 + t]);
        float2 f1 = __half22float2(base[(size_t)(r+1) * 512 + t]);
        float2 f2 = __half22float2(base[(size_t)(r+2) * 512 + t]);
        float2 f3 = __half22float2(base[(size_t)(r+3) * 512 + t]);
        s0.x += f0.x; s0.y += f0.y; s1.x += f1.x; s1.y += f1.y;
        s2.x += f2.x; s2.y += f2.y; s3.x += f3.x; s3.y += f3.y;
    }
    sk[t*2]   = (s0.x + s1.x) + (s2.x + s3.x);
    sk[t*2+1] = (s0.y + s1.y) + (s2.y + s3.y);
    __syncthreads();

    const int warp = t >> 5, lane = t & 31;
    for (int m = warp; m < NB; m += 16) {
        float s = 0.f;
        for (int c = lane; c < HID; c += 32) s += sk[c] * w_sort[c * NB + m];
        #pragma unroll
        for (int o = 16; o; o >>= 1) s += __shfl_xor_sync(0xffffffffu, s, o);
        if (lane == 0) g_sortout[b * (NB*NB) + n * NB + m] = s + b_sort[m];
    }
}

// ---------------------------------------------------------------------------
// Sinkhorn
// ---------------------------------------------------------------------------
__global__ void sinkhorn_kernel() {
    __shared__ float la[32][33];
    __shared__ float colLse[32];
    const int b = blockIdx.x;
    const int j = threadIdx.x, i = threadIdx.y;

    float v = g_sortout[b * (NB*NB) + i * NB + j];

    for (int it = 0; it < 5; it++) {
        float mx = v;
        #pragma unroll
        for (int o = 16; o; o >>= 1) mx = fmaxf(mx, __shfl_xor_sync(0xffffffffu, mx, o));
        float sum = expf(v - mx);
        #pragma unroll
        for (int o = 16; o; o >>= 1) sum += __shfl_xor_sync(0xffffffffu, sum, o);
        v -= mx + logf(sum);

        la[i][j] = v;
        __syncthreads();

        float cv = la[j][i];
        float cm = cv;
        #pragma unroll
        for (int o = 16; o; o >>= 1) cm = fmaxf(cm, __shfl_xor_sync(0xffffffffu, cm, o));
        float cs = expf(cv - cm);
        #pragma unroll
        for (int o = 16; o; o >>= 1) cs += __shfl_xor_sync(0xffffffffu, cs, o);
        if (j == 0) colLse[i] = cm + logf(cs);
        __syncthreads();

        v -= colLse[j];
        __syncthreads();
    }
    g_perm[b * (NB*NB) + i * NB + j] = expf(fminf(fmaxf(v, -1.f), 1.f));
}

// ---------------------------------------------------------------------------
// blockmix via HMMA: sorted[n][s] = perm[n][m] @ Kblk[m][s].
// Per CTA: one token t0 (= blockIdx.x), all 1024 hid; 32 m-rows in smem.
// FIX vs R11/R12: stage ALL 128 16B-chunks per 2048-byte K row (was 64).
// ---------------------------------------------------------------------------
__global__ __launch_bounds__(256, 1)
void blockmix_mma() {
    extern __shared__ __align__(128) char sm[];
    const uint32_t sb = (uint32_t)__cvta_generic_to_shared(sm);
    const uint32_t sK = sb, sP = sb + BM_PERM_OFF;

    const int t0 = blockIdx.x;           // token within block (0..127)
    const int b  = blockIdx.y;
    const int which = blockIdx.z;
    const __half* __restrict__ src = which ? g_v16 : g_k16;
    __half* __restrict__ dst = which ? g_sv16 : g_sk16;

    const int tid = threadIdx.x;
    const int w = tid >> 5, lane = tid & 31;

    // stage K rows: row m = src[b, m*128 + t0, :], 1024 halves = 128 chunks of 16B
    #pragma unroll
    for (int i = 0; i < 16; i++) {
        const int q = tid + i * 256;             // 0..4095
        const int row = q >> 7, ch = q & 127;
        cp16(sK + row * BM_KSTRIDE + ch * 16,
             src + ((size_t)b * PERB + (size_t)row * PERBLK + (size_t)t0 * HID) + ch * 8);
    }
    // stage perm (fp32 -> fp16), 32x32, row stride 80B
    #pragma unroll
    for (int i = 0; i < 4; i++) {
        const int q = tid + i * 256;             // 0..1023
        const int row = q >> 5, col = q & 31;
        *(__half*)(sm + BM_PERM_OFF + row * 80 + col * 2) =
            __float2half_rn(g_perm[b * (NB*NB) + q]);
    }
    CP_COMMIT(); CP_WAIT(0);
    __syncthreads();

    const int mi = lane >> 3, lrow = lane & 7;
    const int g = lane >> 2, t2 = (lane & 3) * 2;

    // A frags: perm rows = n (M dim), cols = m (K dim): 2 m16 x 2 k16
    uint32_t ap[2][2][4];
    #pragma unroll
    for (int mt = 0; mt < 2; mt++)
        #pragma unroll
        for (int kk = 0; kk < 2; kk++)
            ldsm4(ap[mt][kk], sP + (uint32_t)((mt * 16 + (mi & 1) * 8 + lrow) * 80
                                              + (kk * 2 + (mi >> 1)) * 16));

    // per warp: 128 s-cols (w*128 ..), 8 s16-groups
    float acc[2][16][4];
    #pragma unroll
    for (int i = 0; i < 2; i++)
        #pragma unroll
        for (int j = 0; j < 16; j++)
            #pragma unroll
            for (int k = 0; k < 4; k++) acc[i][j][k] = 0.f;

    const int brow_c = (mi & 1) * 8 + lrow;      // row within 16-m group (trans)
    #pragma unroll
    for (int sg = 0; sg < 8; sg++) {             // 16 s-cols per group
        const int ch = w * 16 + sg * 2 + (mi >> 1);  // 16B chunk index
        #pragma unroll
        for (int kk = 0; kk < 2; kk++) {
            uint32_t bb[4];
            ldsm4t(bb, sK + (uint32_t)((kk * 16 + brow_c) * BM_KSTRIDE) + ch * 16);
            #pragma unroll
            for (int mt = 0; mt < 2; mt++) {
                mma16816(acc[mt][sg*2],   ap[mt][kk], bb[0], bb[1]);
                mma16816(acc[mt][sg*2+1], ap[mt][kk], bb[2], bb[3]);
            }
        }
    }

    // store: row n = mt*16 + g (+8 for c2,c3), col = w*128 + nt*8 + t2
    #pragma unroll
    for (int mt = 0; mt < 2; mt++) {
        const int n0 = mt * 16 + g;
        #pragma unroll
        for (int nt = 0; nt < 16; nt++) {
            const int col = w * 128 + nt * 8 + t2;
            const size_t d0 = (size_t)b * PERB + (size_t)n0 * PERBLK
                            + (size_t)t0 * HID + col;
            *(uint32_t*)(dst + d0)                      = packh2(acc[mt][nt][0], acc[mt][nt][1]);
            *(uint32_t*)(dst + d0 + (size_t)8 * PERBLK) = packh2(acc[mt][nt][2], acc[mt][nt][3]);
        }
    }
}

// ---------------------------------------------------------------------------
// Block attention, fp16 HMMA (unchanged)
// ---------------------------------------------------------------------------
__global__ __launch_bounds__(256, 2)
void attn_kernel() {
    extern __shared__ __align__(128) char sm[];
    const uint32_t sb = (uint32_t)__cvta_generic_to_shared(sm);
    const uint32_t sQ = sb, sK = sb + 16384, sV = sb + 49152;

    const int h = blockIdx.x, n = blockIdx.y, b = blockIdx.z;
    const int t = threadIdx.x;
    const int w = t >> 5, lane = t & 31;

    const __half* qg = g_q16 + ((size_t)(b * SEQ + n * BLKS)) * HID + h * HD;
    #pragma unroll
    for (int i = 0; i < 4; i++) {
        const int task = t + i * 256;
        const int row = task >> 3, ch = task & 7;
        cp16(sQ + row * 128 + (((ch ^ row) & 7) << 4), qg + (size_t)row * HID + ch * 8);
    }
    #pragma unroll
    for (int i = 0; i < 8; i++) {
        const int task = t + i * 256;
        const int row = task >> 3, ch = task & 7;
        const __half* kp = (row < BLKS)
            ? g_k16 + ((size_t)(b * SEQ + n * BLKS + row)) * HID + h * HD
            : g_sk16 + (size_t)b * PERB + (size_t)n * PERBLK + (size_t)(row - BLKS) * HID + h * HD;
        cp16(sK + row * 128 + (((ch ^ row) & 7) << 4), kp + ch * 8);
    }
    #pragma unroll
    for (int i = 0; i < 8; i++) {
        const int task = t + i * 256;
        const int row = task >> 3, ch = task & 7;
        const __half* vp = (row < BLKS)
            ? g_v16 + ((size_t)(b * SEQ + n * BLKS + row)) * HID + h * HD
            : g_sv16 + (size_t)b * PERB + (size_t)n * PERBLK + (size_t)(row - BLKS) * HID + h * HD;
        cp16(sV + row * 128 + (((ch ^ row) & 7) << 4), vp + ch * 8);
    }
    CP_COMMIT(); CP_WAIT(0);
    __syncthreads();

    const int mi = lane >> 3, lrow = lane & 7;
    const int g = lane >> 2, t2 = (lane & 3) * 2;

    uint32_t qa[4][4];
    {
        const int qrow = w * 16 + (mi & 1) * 8 + lrow;
        const uint32_t qb = sQ + qrow * 128;
        const int qsw = qrow & 7;
        #pragma unroll
        for (int kt = 0; kt < 4; kt++) {
            const int ch = kt * 2 + (mi >> 1);
            ldsm4(qa[kt], qb + ((ch ^ qsw) << 4));
        }
    }

    float of[8][4];
    #pragma unroll
    for (int i = 0; i < 8; i++)
        #pragma unroll
        for (int j = 0; j < 4; j++) of[i][j] = 0.f;
    float M0 = -1e30f, M1 = -1e30f, p0 = 0.f, p1 = 0.f;

    const int krow_c = (mi >> 1) * 8 + lrow;
    const int vrow_c = (mi & 1) * 8 + lrow;

    for (int kc = 0; kc < 4; kc++) {
        float sc[8][4];
        #pragma unroll
        for (int i = 0; i < 8; i++)
            #pragma unroll
            for (int j = 0; j < 4; j++) sc[i][j] = 0.f;

        #pragma unroll
        for (int kt = 0; kt < 4; kt++) {
            #pragma unroll
            for (int ng = 0; ng < 4; ng++) {
                const int krow = kc * 64 + ng * 16 + krow_c;
                const int ch = kt * 2 + (mi & 1);
                uint32_t kb[4];
                ldsm4(kb, sK + krow * 128 + (((ch ^ krow) & 7) << 4));
                mma16816(sc[ng*2],   qa[kt], kb[0], kb[1]);
                mma16816(sc[ng*2+1], qa[kt], kb[2], kb[3]);
            }
        }
        #pragma unroll
        for (int i = 0; i < 8; i++)
            #pragma unroll
            for (int j = 0; j < 4; j++) sc[i][j] *= 0.125f;

        float m0 = -1e30f, m1 = -1e30f;
        #pragma unroll
        for (int i = 0; i < 8; i++) {
            m0 = fmaxf(m0, fmaxf(sc[i][0], sc[i][1]));
            m1 = fmaxf(m1, fmaxf(sc[i][2], sc[i][3]));
        }
        m0 = fmaxf(m0, __shfl_xor_sync(0xffffffffu, m0, 1));
        m0 = fmaxf(m0, __shfl_xor_sync(0xffffffffu, m0, 2));
        m1 = fmaxf(m1, __shfl_xor_sync(0xffffffffu, m1, 1));
        m1 = fmaxf(m1, __shfl_xor_sync(0xffffffffu, m1, 2));

        const float nM0 = fmaxf(M0, m0), nM1 = fmaxf(M1, m1);
        const float c0 = __expf(M0 - nM0), c1 = __expf(M1 - nM1);
        p0 *= c0; p1 *= c1;
        #pragma unroll
        for (int i = 0; i < 8; i++) {
            of[i][0] *= c0; of[i][1] *= c0;
            of[i][2] *= c1; of[i][3] *= c1;
        }
        M0 = nM0; M1 = nM1;

        #pragma unroll
        for (int i = 0; i < 8; i++) {
            sc[i][0] = __expf(sc[i][0] - M0);
            sc[i][1] = __expf(sc[i][1] - M0);
            sc[i][2] = __expf(sc[i][2] - M1);
            sc[i][3] = __expf(sc[i][3] - M1);
            p0 += sc[i][0] + sc[i][1];
            p1 += sc[i][2] + sc[i][3];
        }

        #pragma unroll
        for (int kt = 0; kt < 4; kt++) {
            uint32_t pa[4];
            pa[0] = packh2(sc[2*kt][0],   sc[2*kt][1]);
            pa[1] = packh2(sc[2*kt][2],   sc[2*kt][3]);
            pa[2] = packh2(sc[2*kt+1][0], sc[2*kt+1][1]);
            pa[3] = packh2(sc[2*kt+1][2], sc[2*kt+1][3]);
            const int vrow = kc * 64 + kt * 16 + vrow_c;
            const uint32_t vb_base = sV + vrow * 128;
            const int vsw = vrow & 7;
            #pragma unroll
            for (int dg = 0; dg < 4; dg++) {
                const int ch = dg * 2 + (mi >> 1);
                uint32_t vb[4];
                ldsm4t(vb, vb_base + ((ch ^ vsw) << 4));
                mma16816(of[dg*2],   pa, vb[0], vb[1]);
                mma16816(of[dg*2+1], pa, vb[2], vb[3]);
            }
        }
    }

    p0 += __shfl_xor_sync(0xffffffffu, p0, 1);
    p0 += __shfl_xor_sync(0xffffffffu, p0, 2);
    p1 += __shfl_xor_sync(0xffffffffu, p1, 1);
    p1 += __shfl_xor_sync(0xffffffffu, p1, 2);
    const float i0 = 1.f / p0, i1 = 1.f / p1;

    const size_t o0 = ((size_t)(b * SEQ + n * BLKS + w * 16 + g)) * HID + h * HD;
    const size_t o1 = o0 + (size_t)8 * HID;
    #pragma unroll
    for (int dg = 0; dg < 8; dg++) {
        *(uint32_t*)(g_x16 + o0 + dg * 8 + t2) = packh2(of[dg][0] * i0, of[dg][1] * i0);
        *(uint32_t*)(g_x16 + o1 + dg * 8 + t2) = packh2(of[dg][2] * i1, of[dg][3] * i1);
    }
}

// ---------------------------------------------------------------------------
// Host launcher
// ---------------------------------------------------------------------------
extern "C" void kernel_launch(void* const* d_in, const int* in_sizes, int n_in,
                              void* d_out, int out_size) {
    const float* inputs_q = (const float*)d_in[0];
    const float* wq = (const float*)d_in[1];
    const float* bq = (const float*)d_in[2];
    const float* wk = (const float*)d_in[3];
    const float* bk = (const float*)d_in[4];
    const float* wv = (const float*)d_in[5];
    const float* bv = (const float*)d_in[6];
    const float* w_sort = (const float*)d_in[7];
    const float* b_sort = (const float*)d_in[8];
    const float* wo = (const float*)d_in[9];
    const float* bo = (const float*)d_in[10];
    float* out = (float*)d_out;

    __half *a16, *q16, *k16, *v16, *x16, *wq16, *wk16, *wv16, *wo16;
    cudaGetSymbolAddress((void**)&a16,  g_a16);
    cudaGetSymbolAddress((void**)&q16,  g_q16);
    cudaGetSymbolAddress((void**)&k16,  g_k16);
    cudaGetSymbolAddress((void**)&v16,  g_v16);
    cudaGetSymbolAddress((void**)&x16,  g_x16);
    cudaGetSymbolAddress((void**)&wq16, g_wq16);
    cudaGetSymbolAddress((void**)&wk16, g_wk16);
    cudaGetSymbolAddress((void**)&wv16, g_wv16);
    cudaGetSymbolAddress((void**)&wo16, g_wo16);

    cudaFuncSetAttribute(gemm_hmma, cudaFuncAttributeMaxDynamicSharedMemorySize, GEMM_SMEM);
    cudaFuncSetAttribute(attn_kernel, cudaFuncAttributeMaxDynamicSharedMemorySize, ATT_SMEM);
    cudaFuncSetAttribute(blockmix_mma, cudaFuncAttributeMaxDynamicSharedMemorySize, BM_SMEM);

    const int n4 = ROWS * DM / 4;
    to_half<<<(n4 + 255) / 256, 256>>>(inputs_q, a16, n4);
    transpose_half4<<<dim3(32, 32, 4), dim3(32, 8)>>>(wq, wk, wv, wo,
                                                      wq16, wk16, wv16, wo16);

    // Fused Q/K/V projection: grid.z selects weight/bias/output
    gemm_hmma<<<dim3(HID / TN, ROWS / TM, 3), 256, GEMM_SMEM>>>(
        a16, wq16, wk16, wv16, bq, bk, bv, nullptr, q16, k16, v16);

    sumkey_sort<<<BS * NB, 512>>>(w_sort, b_sort);
    sinkhorn_kernel<<<BS, dim3(32, 32)>>>();
    blockmix_mma<<<dim3(BLKS, BS, 2), 256, BM_SMEM>>>();
    attn_kernel<<<dim3(NH, NB, BS), 256, ATT_SMEM>>>();

    // Output projection (fp32 out)
    gemm_hmma<<<dim3(HID / TN, ROWS / TM, 1), 256, GEMM_SMEM>>>(
        x16, wo16, wo16, wo16, bo, bo, bo, out, nullptr, nullptr, nullptr);
}

// round 14
// speedup vs baseline: 7.0497x; 1.0069x over previous
#include <cuda_runtime.h>
#include <cuda_fp16.h>
#include <cstdint>

// ---------------------------------------------------------------------------
// SinkhornAttention: BS=4, SEQ=4096, DM=1024, H=16, HD=64, BLK=128, NB=32
// ---------------------------------------------------------------------------
#define BS   4
#define SEQ  4096
#define DM   1024
#define NH   16
#define HD   64
#define BLKS 128
#define NB   32
#define ROWS (BS*SEQ)            // 16384
#define HID  (NH*HD)             // 1024
#define PERB (SEQ*HID)           // 4194304 (elements per batch)
#define PERBLK (BLKS*HID)        // 131072

// GEMM tiling: CTA 128x256, 8 warps (2M x 4N), warp tile 64x64, KC=64
#define TM 128
#define TN 256
#define KC 64
#define NCHUNK (DM / KC)            // 16
#define ROWB 144                    // 128B data + 16B pad per 64-k row
#define MATB_A (128 * ROWB)         // 18432
#define MATB_B (256 * ROWB)         // 36864
#define STAGE_BYTES (MATB_A + MATB_B)  // 55296
#define NSTAGE 3
#define GEMM_SMEM (NSTAGE * STAGE_BYTES)   // 165888

// Attention smem: Q 16KB @0, K 32KB @16384, V 32KB @49152
#define ATT_SMEM 81920

// blockmix smem: K rows 32 x (2048B + 16 pad) + perm 32*80
#define BM_KSTRIDE 2064
#define BM_PERM_OFF (32 * BM_KSTRIDE)        // 66048
#define BM_SMEM (BM_PERM_OFF + 32 * 80)      // 68608

// ---------------------------------------------------------------------------
// Scratch (device globals: allocation-free per harness rules)
// ---------------------------------------------------------------------------
__device__ float g_sortout[BS*NB*NB];
__device__ float g_perm   [BS*NB*NB];

__device__ __half g_a16[ROWS*DM];    // inputs_q fp16
__device__ __half g_q16[ROWS*HID];
__device__ __half g_k16[ROWS*HID];
__device__ __half g_v16[ROWS*HID];
__device__ __half g_sk16[ROWS*HID];
__device__ __half g_sv16[ROWS*HID];
__device__ __half g_x16[ROWS*HID];
__device__ __half g_wq16[HID*DM];    // transposed [n][k]
__device__ __half g_wk16[HID*DM];
__device__ __half g_wv16[HID*DM];
__device__ __half g_wo16[DM*HID];

// ---------------------------------------------------------------------------
// PTX helpers
// ---------------------------------------------------------------------------
__device__ __forceinline__ void cp16(uint32_t s, const void* g) {
    asm volatile("cp.async.cg.shared.global [%0], [%1], 16;" :: "r"(s), "l"(g));
}
#define CP_COMMIT() asm volatile("cp.async.commit_group;" ::: "memory")
#define CP_WAIT(n)  asm volatile("cp.async.wait_group %0;" :: "n"(n) : "memory")

__device__ __forceinline__ void ldsm4(uint32_t* r, uint32_t addr) {
    asm volatile("ldmatrix.sync.aligned.m8n8.x4.shared.b16 {%0,%1,%2,%3}, [%4];"
                 : "=r"(r[0]), "=r"(r[1]), "=r"(r[2]), "=r"(r[3]) : "r"(addr));
}
__device__ __forceinline__ void ldsm4t(uint32_t* r, uint32_t addr) {
    asm volatile("ldmatrix.sync.aligned.m8n8.x4.trans.shared.b16 {%0,%1,%2,%3}, [%4];"
                 : "=r"(r[0]), "=r"(r[1]), "=r"(r[2]), "=r"(r[3]) : "r"(addr));
}
__device__ __forceinline__ void mma16816(float* c, const uint32_t* a,
                                         uint32_t b0, uint32_t b1) {
    asm volatile("mma.sync.aligned.m16n8k16.row.col.f32.f16.f16.f32 "
                 "{%0,%1,%2,%3}, {%4,%5,%6,%7}, {%8,%9}, {%0,%1,%2,%3};"
                 : "+f"(c[0]), "+f"(c[1]), "+f"(c[2]), "+f"(c[3])
                 : "r"(a[0]), "r"(a[1]), "r"(a[2]), "r"(a[3]), "r"(b0), "r"(b1));
}
__device__ __forceinline__ uint32_t packh2(float a, float b) {
    __half2 h = __floats2half2_rn(a, b);
    return *(uint32_t*)&h;
}

// ---------------------------------------------------------------------------
// Convert fp32 -> fp16 (4x float4 per thread for MLP)
// ---------------------------------------------------------------------------
__global__ __launch_bounds__(256)
void to_half(const float* __restrict__ src, __half* __restrict__ dst, int n4) {
    int i = (blockIdx.x * 256 + threadIdx.x) * 4;
    #pragma unroll
    for (int j = 0; j < 4; j++) {
        if (i + j >= n4) return;
        float4 f = ((const float4*)src)[i + j];
        __half2 h0, h1;
        h0.x = __float2half_rn(f.x); h0.y = __float2half_rn(f.y);
        h1.x = __float2half_rn(f.z); h1.y = __float2half_rn(f.w);
        ((__half2*)dst)[(i + j) * 2]     = h0;
        ((__half2*)dst)[(i + j) * 2 + 1] = h1;
    }
}

// ---------------------------------------------------------------------------
// Transpose 4x 1024x1024 fp32 W[k][n] -> fp16 Wt[n][k], fused (grid.z selects)
// ---------------------------------------------------------------------------
__global__ __launch_bounds__(256)
void transpose_half4(const float* __restrict__ W0, const float* __restrict__ W1,
                     const float* __restrict__ W2, const float* __restrict__ W3,
                     __half* __restrict__ T0, __half* __restrict__ T1,
                     __half* __restrict__ T2, __half* __restrict__ T3) {
    const float* W = (blockIdx.z == 0) ? W0 : (blockIdx.z == 1) ? W1
                   : (blockIdx.z == 2) ? W2 : W3;
    __half* T = (blockIdx.z == 0) ? T0 : (blockIdx.z == 1) ? T1
              : (blockIdx.z == 2) ? T2 : T3;
    __shared__ float t[32][33];
    const int tx = threadIdx.x, ty = threadIdx.y;
    const int x = blockIdx.x * 32 + tx;
    const int y0 = blockIdx.y * 32;
    #pragma unroll
    for (int i = ty; i < 32; i += 8) t[i][tx] = W[(size_t)(y0 + i) * 1024 + x];
    __syncthreads();
    const int k = y0 + tx;
    #pragma unroll
    for (int i = ty; i < 32; i += 8) {
        int n = blockIdx.x * 32 + i;
        T[(size_t)n * 1024 + k] = __float2half_rn(t[tx][i]);
    }
}

// ---------------------------------------------------------------------------
// HMMA GEMM, KC=64, 3-stage cp.async, cross-k16 fragment double-buffering.
// grid.z selects (B, bias, out). fp32 out (Cf) when non-null else fp16 (Ch).
// ---------------------------------------------------------------------------
__global__ __launch_bounds__(256, 1)
void gemm_hmma(const __half* __restrict__ A,
               const __half* __restrict__ B0, const __half* __restrict__ B1,
               const __half* __restrict__ B2,
               const float* __restrict__ bi0, const float* __restrict__ bi1,
               const float* __restrict__ bi2,
               float* __restrict__ Cf,
               __half* __restrict__ Ch0, __half* __restrict__ Ch1,
               __half* __restrict__ Ch2) {
    const int z = blockIdx.z;
    const __half* __restrict__ B  = (z == 0) ? B0 : (z == 1) ? B1 : B2;
    const float* __restrict__ bias = (z == 0) ? bi0 : (z == 1) ? bi1 : bi2;
    __half* __restrict__ Ch = (z == 0) ? Ch0 : (z == 1) ? Ch1 : Ch2;

    extern __shared__ __align__(128) char smem[];
    const uint32_t sbase = (uint32_t)__cvta_generic_to_shared(smem);

    const int tid  = threadIdx.x;
    const int wid  = tid >> 5, lane = tid & 31;
    const int wm   = wid >> 2;
    const int wn   = wid & 3;
    const int bx0  = blockIdx.x * TN;
    const int by0  = blockIdx.y * TM;

    auto load_stage = [&](int c, int s) {
        const uint32_t st = sbase + (uint32_t)s * STAGE_BYTES;
        const size_t k0 = (size_t)c * KC;
        #pragma unroll
        for (int i = 0; i < 4; i++) {             // A: 128 rows x 8 chunks of 16B
            const int q = tid + i * 256;
            const int row = q >> 3, ch = q & 7;
            cp16(st + (uint32_t)(row * ROWB + ch * 16),
                 A + (size_t)(by0 + row) * DM + k0 + ch * 8);
        }
        #pragma unroll
        for (int i = 0; i < 8; i++) {             // B: 256 rows x 8 chunks
            const int q = tid + i * 256;
            const int row = q >> 3, ch = q & 7;
            cp16(st + MATB_A + (uint32_t)(row * ROWB + ch * 16),
                 B + (size_t)(bx0 + row) * DM + k0 + ch * 8);
        }
    };

    const int mi   = lane >> 3;
    const int lrow = lane & 7;
    const uint32_t aoff = (uint32_t)(((mi & 1) * 8 + lrow) * ROWB + (mi >> 1) * 16);
    const uint32_t boff = (uint32_t)(((mi >> 1) * 8 + lrow) * ROWB + (mi & 1) * 16);

    float acc[4][8][4];
    #pragma unroll
    for (int i = 0; i < 4; i++)
        #pragma unroll
        for (int j = 0; j < 8; j++)
            #pragma unroll
            for (int k = 0; k < 4; k++) acc[i][j][k] = 0.f;

    load_stage(0, 0); CP_COMMIT();
    load_stage(1, 1); CP_COMMIT();

    for (int c = 0; c < NCHUNK; c++) {
        CP_WAIT(1);
        __syncthreads();

        const uint32_t st = sbase + (uint32_t)(c % 3) * STAGE_BYTES;
        const uint32_t sA = st, sB = st + MATB_A;

        auto ldfrag = [&](int ks, uint32_t (&a)[4][4], uint32_t (&b)[4][4]) {
            const uint32_t kb = (uint32_t)ks * 32;
            #pragma unroll
            for (int mt = 0; mt < 4; mt++)
                ldsm4(a[mt], sA + (uint32_t)((wm * 64 + mt * 16) * ROWB) + kb + aoff);
            #pragma unroll
            for (int nb = 0; nb < 4; nb++)
                ldsm4(b[nb], sB + (uint32_t)((wn * 64 + nb * 16) * ROWB) + kb + boff);
        };

        uint32_t a[2][4][4], b[2][4][4];
        ldfrag(0, a[0], b[0]);

        #pragma unroll
        for (int ks = 0; ks < 4; ks++) {
            const int cur = ks & 1;
            if (ks < 3) ldfrag(ks + 1, a[cur ^ 1], b[cur ^ 1]);
            if (ks == 1) {
                if (c + 2 < NCHUNK) load_stage(c + 2, (c + 2) % 3);
                CP_COMMIT();
            }
            #pragma unroll
            for (int mt = 0; mt < 4; mt++)
                #pragma unroll
                for (int nt = 0; nt < 8; nt++) {
                    const int p = nt >> 1, q = (nt & 1) * 2;
                    mma16816(acc[mt][nt], a[cur][mt], b[cur][p][q], b[cur][p][q+1]);
                }
        }
    }

    const int g = lane >> 2, t2 = (lane & 3) * 2;
    #pragma unroll
    for (int mt = 0; mt < 4; mt++) {
        const int row0 = by0 + wm * 64 + mt * 16 + g;
        #pragma unroll
        for (int nt = 0; nt < 8; nt++) {
            const int col = bx0 + wn * 64 + nt * 8 + t2;
            const float2 bv = *(const float2*)(bias + col);
            float o00 = acc[mt][nt][0] + bv.x, o01 = acc[mt][nt][1] + bv.y;
            float o10 = acc[mt][nt][2] + bv.x, o11 = acc[mt][nt][3] + bv.y;
            if (Cf) {
                *(float2*)(Cf + (size_t)row0 * HID + col)       = make_float2(o00, o01);
                *(float2*)(Cf + (size_t)(row0 + 8) * HID + col) = make_float2(o10, o11);
            } else {
                *(uint32_t*)(Ch + (size_t)row0 * HID + col)       = packh2(o00, o01);
                *(uint32_t*)(Ch + (size_t)(row0 + 8) * HID + col) = packh2(o10, o11);
            }
        }
    }
}

// ---------------------------------------------------------------------------
// sum_key + sort logits: 512 threads, half2 columns, MLP-unrolled row loop
// ---------------------------------------------------------------------------
__global__ __launch_bounds__(512)
void sumkey_sort(const float* __restrict__ w_sort, const float* __restrict__ b_sort) {
    __shared__ float sk[HID];
    const int bn = blockIdx.x;
    const int b = bn >> 5, n = bn & 31;
    const int t = threadIdx.x;        // 0..511 = half2 column

    const __half2* base = (const __half2*)(g_k16 + ((size_t)(b * SEQ + n * BLKS)) * HID);
    float2 s0 = {0.f,0.f}, s1 = {0.f,0.f}, s2 = {0.f,0.f}, s3 = {0.f,0.f};
    #pragma unroll 8
    for (int r = 0; r < BLKS; r += 4) {
        float2 f0 = __half22float2(base[(size_t)(r+0) * 512 + t]);
        float2 f1 = __half22float2(base[(size_t)(r+1) * 512 + t]);
        float2 f2 = __half22float2(base[(size_t)(r+2) * 512 + t]);
        float2 f3 = __half22float2(base[(size_t)(r+3) * 512 + t]);
        s0.x += f0.x; s0.y += f0.y; s1.x += f1.x; s1.y += f1.y;
        s2.x += f2.x; s2.y += f2.y; s3.x += f3.x; s3.y += f3.y;
    }
    sk[t*2]   = (s0.x + s1.x) + (s2.x + s3.x);
    sk[t*2+1] = (s0.y + s1.y) + (s2.y + s3.y);
    __syncthreads();

    const int warp = t >> 5, lane = t & 31;
    for (int m = warp; m < NB; m += 16) {
        float s = 0.f;
        for (int c = lane; c < HID; c += 32) s += sk[c] * w_sort[c * NB + m];
        #pragma unroll
        for (int o = 16; o; o >>= 1) s += __shfl_xor_sync(0xffffffffu, s, o);
        if (lane == 0) g_sortout[b * (NB*NB) + n * NB + m] = s + b_sort[m];
    }
}

// ---------------------------------------------------------------------------
// Sinkhorn
// ---------------------------------------------------------------------------
__global__ void sinkhorn_kernel() {
    __shared__ float la[32][33];
    __shared__ float colLse[32];
    const int b = blockIdx.x;
    const int j = threadIdx.x, i = threadIdx.y;

    float v = g_sortout[b * (NB*NB) + i * NB + j];

    for (int it = 0; it < 5; it++) {
        float mx = v;
        #pragma unroll
        for (int o = 16; o; o >>= 1) mx = fmaxf(mx, __shfl_xor_sync(0xffffffffu, mx, o));
        float sum = expf(v - mx);
        #pragma unroll
        for (int o = 16; o; o >>= 1) sum += __shfl_xor_sync(0xffffffffu, sum, o);
        v -= mx + logf(sum);

        la[i][j] = v;
        __syncthreads();

        float cv = la[j][i];
        float cm = cv;
        #pragma unroll
        for (int o = 16; o; o >>= 1) cm = fmaxf(cm, __shfl_xor_sync(0xffffffffu, cm, o));
        float cs = expf(cv - cm);
        #pragma unroll
        for (int o = 16; o; o >>= 1) cs += __shfl_xor_sync(0xffffffffu, cs, o);
        if (j == 0) colLse[i] = cm + logf(cs);
        __syncthreads();

        v -= colLse[j];
        __syncthreads();
    }
    g_perm[b * (NB*NB) + i * NB + j] = expf(fminf(fmaxf(v, -1.f), 1.f));
}

// ---------------------------------------------------------------------------
// blockmix via HMMA (R13-proven): sorted[n][s] = perm[n][m] @ Kblk[m][s].
// ---------------------------------------------------------------------------
__global__ __launch_bounds__(256, 1)
void blockmix_mma() {
    extern __shared__ __align__(128) char sm[];
    const uint32_t sb = (uint32_t)__cvta_generic_to_shared(sm);
    const uint32_t sK = sb, sP = sb + BM_PERM_OFF;

    const int t0 = blockIdx.x;           // token within block (0..127)
    const int b  = blockIdx.y;
    const int which = blockIdx.z;
    const __half* __restrict__ src = which ? g_v16 : g_k16;
    __half* __restrict__ dst = which ? g_sv16 : g_sk16;

    const int tid = threadIdx.x;
    const int w = tid >> 5, lane = tid & 31;

    // stage K rows: row m = src[b, m*128 + t0, :], 1024 halves = 128 chunks of 16B
    #pragma unroll
    for (int i = 0; i < 16; i++) {
        const int q = tid + i * 256;             // 0..4095
        const int row = q >> 7, ch = q & 127;
        cp16(sK + row * BM_KSTRIDE + ch * 16,
             src + ((size_t)b * PERB + (size_t)row * PERBLK + (size_t)t0 * HID) + ch * 8);
    }
    // stage perm (fp32 -> fp16), 32x32, row stride 80B
    #pragma unroll
    for (int i = 0; i < 4; i++) {
        const int q = tid + i * 256;             // 0..1023
        const int row = q >> 5, col = q & 31;
        *(__half*)(sm + BM_PERM_OFF + row * 80 + col * 2) =
            __float2half_rn(g_perm[b * (NB*NB) + q]);
    }
    CP_COMMIT(); CP_WAIT(0);
    __syncthreads();

    const int mi = lane >> 3, lrow = lane & 7;
    const int g = lane >> 2, t2 = (lane & 3) * 2;

    // A frags: perm rows = n (M dim), cols = m (K dim): 2 m16 x 2 k16
    uint32_t ap[2][2][4];
    #pragma unroll
    for (int mt = 0; mt < 2; mt++)
        #pragma unroll
        for (int kk = 0; kk < 2; kk++)
            ldsm4(ap[mt][kk], sP + (uint32_t)((mt * 16 + (mi & 1) * 8 + lrow) * 80
                                              + (kk * 2 + (mi >> 1)) * 16));

    // per warp: 128 s-cols (w*128 ..), 8 s16-groups
    float acc[2][16][4];
    #pragma unroll
    for (int i = 0; i < 2; i++)
        #pragma unroll
        for (int j = 0; j < 16; j++)
            #pragma unroll
            for (int k = 0; k < 4; k++) acc[i][j][k] = 0.f;

    const int brow_c = (mi & 1) * 8 + lrow;      // row within 16-m group (trans)
    #pragma unroll
    for (int sg = 0; sg < 8; sg++) {             // 16 s-cols per group
        const int ch = w * 16 + sg * 2 + (mi >> 1);  // 16B chunk index
        #pragma unroll
        for (int kk = 0; kk < 2; kk++) {
            uint32_t bb[4];
            ldsm4t(bb, sK + (uint32_t)((kk * 16 + brow_c) * BM_KSTRIDE) + ch * 16);
            #pragma unroll
            for (int mt = 0; mt < 2; mt++) {
                mma16816(acc[mt][sg*2],   ap[mt][kk], bb[0], bb[1]);
                mma16816(acc[mt][sg*2+1], ap[mt][kk], bb[2], bb[3]);
            }
        }
    }

    // store: row n = mt*16 + g (+8 for c2,c3), col = w*128 + nt*8 + t2
    #pragma unroll
    for (int mt = 0; mt < 2; mt++) {
        const int n0 = mt * 16 + g;
        #pragma unroll
        for (int nt = 0; nt < 16; nt++) {
            const int col = w * 128 + nt * 8 + t2;
            const size_t d0 = (size_t)b * PERB + (size_t)n0 * PERBLK
                            + (size_t)t0 * HID + col;
            *(uint32_t*)(dst + d0)                      = packh2(acc[mt][nt][0], acc[mt][nt][1]);
            *(uint32_t*)(dst + d0 + (size_t)8 * PERBLK) = packh2(acc[mt][nt][2], acc[mt][nt][3]);
        }
    }
}

// ---------------------------------------------------------------------------
// Block attention, fp16 HMMA (unchanged)
// ---------------------------------------------------------------------------
__global__ __launch_bounds__(256, 2)
void attn_kernel() {
    extern __shared__ __align__(128) char sm[];
    const uint32_t sb = (uint32_t)__cvta_generic_to_shared(sm);
    const uint32_t sQ = sb, sK = sb + 16384, sV = sb + 49152;

    const int h = blockIdx.x, n = blockIdx.y, b = blockIdx.z;
    const int t = threadIdx.x;
    const int w = t >> 5, lane = t & 31;

    const __half* qg = g_q16 + ((size_t)(b * SEQ + n * BLKS)) * HID + h * HD;
    #pragma unroll
    for (int i = 0; i < 4; i++) {
        const int task = t + i * 256;
        const int row = task >> 3, ch = task & 7;
        cp16(sQ + row * 128 + (((ch ^ row) & 7) << 4), qg + (size_t)row * HID + ch * 8);
    }
    #pragma unroll
    for (int i = 0; i < 8; i++) {
        const int task = t + i * 256;
        const int row = task >> 3, ch = task & 7;
        const __half* kp = (row < BLKS)
            ? g_k16 + ((size_t)(b * SEQ + n * BLKS + row)) * HID + h * HD
            : g_sk16 + (size_t)b * PERB + (size_t)n * PERBLK + (size_t)(row - BLKS) * HID + h * HD;
        cp16(sK + row * 128 + (((ch ^ row) & 7) << 4), kp + ch * 8);
    }
    #pragma unroll
    for (int i = 0; i < 8; i++) {
        const int task = t + i * 256;
        const int row = task >> 3, ch = task & 7;
        const __half* vp = (row < BLKS)
            ? g_v16 + ((size_t)(b * SEQ + n * BLKS + row)) * HID + h * HD
            : g_sv16 + (size_t)b * PERB + (size_t)n * PERBLK + (size_t)(row - BLKS) * HID + h * HD;
        cp16(sV + row * 128 + (((ch ^ row) & 7) << 4), vp + ch * 8);
    }
    CP_COMMIT(); CP_WAIT(0);
    __syncthreads();

    const int mi = lane >> 3, lrow = lane & 7;
    const int g = lane >> 2, t2 = (lane & 3) * 2;

    uint32_t qa[4][4];
    {
        const int qrow = w * 16 + (mi & 1) * 8 + lrow;
        const uint32_t qb = sQ + qrow * 128;
        const int qsw = qrow & 7;
        #pragma unroll
        for (int kt = 0; kt < 4; kt++) {
            const int ch = kt * 2 + (mi >> 1);
            ldsm4(qa[kt], qb + ((ch ^ qsw) << 4));
        }
    }

    float of[8][4];
    #pragma unroll
    for (int i = 0; i < 8; i++)
        #pragma unroll
        for (int j = 0; j < 4; j++) of[i][j] = 0.f;
    float M0 = -1e30f, M1 = -1e30f, p0 = 0.f, p1 = 0.f;

    const int krow_c = (mi >> 1) * 8 + lrow;
    const int vrow_c = (mi & 1) * 8 + lrow;

    for (int kc = 0; kc < 4; kc++) {
        float sc[8][4];
        #pragma unroll
        for (int i = 0; i < 8; i++)
            #pragma unroll
            for (int j = 0; j < 4; j++) sc[i][j] = 0.f;

        #pragma unroll
        for (int kt = 0; kt < 4; kt++) {
            #pragma unroll
            for (int ng = 0; ng < 4; ng++) {
                const int krow = kc * 64 + ng * 16 + krow_c;
                const int ch = kt * 2 + (mi & 1);
                uint32_t kb[4];
                ldsm4(kb, sK + krow * 128 + (((ch ^ krow) & 7) << 4));
                mma16816(sc[ng*2],   qa[kt], kb[0], kb[1]);
                mma16816(sc[ng*2+1], qa[kt], kb[2], kb[3]);
            }
        }
        #pragma unroll
        for (int i = 0; i < 8; i++)
            #pragma unroll
            for (int j = 0; j < 4; j++) sc[i][j] *= 0.125f;

        float m0 = -1e30f, m1 = -1e30f;
        #pragma unroll
        for (int i = 0; i < 8; i++) {
            m0 = fmaxf(m0, fmaxf(sc[i][0], sc[i][1]));
            m1 = fmaxf(m1, fmaxf(sc[i][2], sc[i][3]));
        }
        m0 = fmaxf(m0, __shfl_xor_sync(0xffffffffu, m0, 1));
        m0 = fmaxf(m0, __shfl_xor_sync(0xffffffffu, m0, 2));
        m1 = fmaxf(m1, __shfl_xor_sync(0xffffffffu, m1, 1));
        m1 = fmaxf(m1, __shfl_xor_sync(0xffffffffu, m1, 2));

        const float nM0 = fmaxf(M0, m0), nM1 = fmaxf(M1, m1);
        const float c0 = __expf(M0 - nM0), c1 = __expf(M1 - nM1);
        p0 *= c0; p1 *= c1;
        #pragma unroll
        for (int i = 0; i < 8; i++) {
            of[i][0] *= c0; of[i][1] *= c0;
            of[i][2] *= c1; of[i][3] *= c1;
        }
        M0 = nM0; M1 = nM1;

        #pragma unroll
        for (int i = 0; i < 8; i++) {
            sc[i][0] = __expf(sc[i][0] - M0);
            sc[i][1] = __expf(sc[i][1] - M0);
            sc[i][2] = __expf(sc[i][2] - M1);
            sc[i][3] = __expf(sc[i][3] - M1);
            p0 += sc[i][0] + sc[i][1];
            p1 += sc[i][2] + sc[i][3];
        }

        #pragma unroll
        for (int kt = 0; kt < 4; kt++) {
            uint32_t pa[4];
            pa[0] = packh2(sc[2*kt][0],   sc[2*kt][1]);
            pa[1] = packh2(sc[2*kt][2],   sc[2*kt][3]);
            pa[2] = packh2(sc[2*kt+1][0], sc[2*kt+1][1]);
            pa[3] = packh2(sc[2*kt+1][2], sc[2*kt+1][3]);
            const int vrow = kc * 64 + kt * 16 + vrow_c;
            const uint32_t vb_base = sV + vrow * 128;
            const int vsw = vrow & 7;
            #pragma unroll
            for (int dg = 0; dg < 4; dg++) {
                const int ch = dg * 2 + (mi >> 1);
                uint32_t vb[4];
                ldsm4t(vb, vb_base + ((ch ^ vsw) << 4));
                mma16816(of[dg*2],   pa, vb[0], vb[1]);
                mma16816(of[dg*2+1], pa, vb[2], vb[3]);
            }
        }
    }

    p0 += __shfl_xor_sync(0xffffffffu, p0, 1);
    p0 += __shfl_xor_sync(0xffffffffu, p0, 2);
    p1 += __shfl_xor_sync(0xffffffffu, p1, 1);
    p1 += __shfl_xor_sync(0xffffffffu, p1, 2);
    const float i0 = 1.f / p0, i1 = 1.f / p1;

    const size_t o0 = ((size_t)(b * SEQ + n * BLKS + w * 16 + g)) * HID + h * HD;
    const size_t o1 = o0 + (size_t)8 * HID;
    #pragma unroll
    for (int dg = 0; dg < 8; dg++) {
        *(uint32_t*)(g_x16 + o0 + dg * 8 + t2) = packh2(of[dg][0] * i0, of[dg][1] * i0);
        *(uint32_t*)(g_x16 + o1 + dg * 8 + t2) = packh2(of[dg][2] * i1, of[dg][3] * i1);
    }
}

// ---------------------------------------------------------------------------
// Host launcher
// ---------------------------------------------------------------------------
extern "C" void kernel_launch(void* const* d_in, const int* in_sizes, int n_in,
                              void* d_out, int out_size) {
    const float* inputs_q = (const float*)d_in[0];
    const float* wq = (const float*)d_in[1];
    const float* bq = (const float*)d_in[2];
    const float* wk = (const float*)d_in[3];
    const float* bk = (const float*)d_in[4];
    const float* wv = (const float*)d_in[5];
    const float* bv = (const float*)d_in[6];
    const float* w_sort = (const float*)d_in[7];
    const float* b_sort = (const float*)d_in[8];
    const float* wo = (const float*)d_in[9];
    const float* bo = (const float*)d_in[10];
    float* out = (float*)d_out;

    __half *a16, *q16, *k16, *v16, *x16, *wq16, *wk16, *wv16, *wo16;
    cudaGetSymbolAddress((void**)&a16,  g_a16);
    cudaGetSymbolAddress((void**)&q16,  g_q16);
    cudaGetSymbolAddress((void**)&k16,  g_k16);
    cudaGetSymbolAddress((void**)&v16,  g_v16);
    cudaGetSymbolAddress((void**)&x16,  g_x16);
    cudaGetSymbolAddress((void**)&wq16, g_wq16);
    cudaGetSymbolAddress((void**)&wk16, g_wk16);
    cudaGetSymbolAddress((void**)&wv16, g_wv16);
    cudaGetSymbolAddress((void**)&wo16, g_wo16);

    cudaFuncSetAttribute(gemm_hmma, cudaFuncAttributeMaxDynamicSharedMemorySize, GEMM_SMEM);
    cudaFuncSetAttribute(attn_kernel, cudaFuncAttributeMaxDynamicSharedMemorySize, ATT_SMEM);
    cudaFuncSetAttribute(blockmix_mma, cudaFuncAttributeMaxDynamicSharedMemorySize, BM_SMEM);

    const int n4 = ROWS * DM / 4;
    to_half<<<(n4 / 4 + 255) / 256, 256>>>(inputs_q, a16, n4);
    transpose_half4<<<dim3(32, 32, 4), dim3(32, 8)>>>(wq, wk, wv, wo,
                                                      wq16, wk16, wv16, wo16);

    // Fused Q/K/V projection: grid.z selects weight/bias/output
    gemm_hmma<<<dim3(HID / TN, ROWS / TM, 3), 256, GEMM_SMEM>>>(
        a16, wq16, wk16, wv16, bq, bk, bv, nullptr, q16, k16, v16);

    sumkey_sort<<<BS * NB, 512>>>(w_sort, b_sort);
    sinkhorn_kernel<<<BS, dim3(32, 32)>>>();
    blockmix_mma<<<dim3(BLKS, BS, 2), 256, BM_SMEM>>>();
    attn_kernel<<<dim3(NH, NB, BS), 256, ATT_SMEM>>>();

    // Output projection (fp32 out)
    gemm_hmma<<<dim3(HID / TN, ROWS / TM, 1), 256, GEMM_SMEM>>>(
        x16, wo16, wo16, wo16, bo, bo, bo, out, nullptr, nullptr, nullptr);
}